// round 12
// baseline (speedup 1.0000x reference)
#include <cuda_runtime.h>
#include <cuda_fp16.h>
#include <cstdint>
#include <math.h>

#define NQ 10000
#define NE 320000
#define KNBR 10
#define CDIM 128
#define MPAD 10048
#define GS 50
#define NCELL 2500
#define ESTRIDE 128                           // padded CSR slots per node

// taps stored scaled by 8^-k (exact exponent shifts); weights by 8^k.
#define TAP_DOWN 0.125f

// ---------------- scratch (device globals; no allocation allowed) ----------
__device__ float  g_x[MPAD * CDIM];          // node features (residual stream, fp32)
__device__ __half g_Hh[MPAD * 512];          // centered taps [h0'|h1'/8|h2'/64|h3'/512]
__device__ __half g_WhT[2 * 128 * 512];      // gf_W transposed [l][n][k], W_k * 8^k
__device__ float  g_y[MPAD * CDIM];          // graph-filter output
__device__ int    g_deg[NQ];                 // degree (also scatter cursor)
__device__ int    g_esrc[NQ * ESTRIDE];      // padded CSR: sources per dst
__device__ float  g_stats[256];              // [sum(128) | sumsq(128)]
// mean-correction machinery
__device__ float  g_cpart[128 * 128];        // partial column sums
__device__ float  g_corr[3 * 128];           // c_k = xbar @ W_k  (k=1..3)
__device__ float  g_dd2[MPAD];               // S^2 1
__device__ float  g_dd3[MPAD];               // S^3 1
// spatial grid (agents then targets)
__device__ int    g_ccnt[2 * NCELL];
__device__ int    g_coff[2 * (NCELL + 1)];
__device__ int    g_ccur[2 * NCELL];
__device__ float2 g_cpos[2 * NQ];
__device__ int    g_cidx[2 * NQ];
__device__ int    g_aidx_buf[NQ * KNBR];
__device__ int    g_tidx_buf[NQ * KNBR];

// ---------------- 0) init: zero counters/deg + convert weights -------------
__global__ void init_kernel(const float* __restrict__ gfW) {
    int t = blockIdx.x * blockDim.x + threadIdx.x;
    if (t < 2 * NCELL) g_ccnt[t] = 0;
    if (t < NQ) g_deg[t] = 0;
    // WhT[l][n][k] = gf_W[l][k][n] * 8^(k/128), fp16
    for (int i = t; i < 2 * 512 * 128; i += gridDim.x * blockDim.x) {
        int l = i >> 16;
        int rem = i & 65535;
        int n = rem >> 9;
        int k = rem & 511;
        float up = (k < 128) ? 1.f : (k < 256) ? 8.f : (k < 384) ? 64.f : 512.f;
        g_WhT[i] = __float2half(gfW[(l << 16) + k * 128 + n] * up);
    }
}

// ---------------- 1) fused: cell counts (points only) + self MLP -----------
__device__ __forceinline__ int cell_of(float v) {
    int c = __float2int_rd(v * 0.5f);
    return min(max(c, 0), GS - 1);
}
__global__ void count_selfmlp_kernel(const float* __restrict__ apos,
                                     const float* __restrict__ tpos,
                                     const float* __restrict__ obs,
                                     const float* __restrict__ Ws,
                                     const float* __restrict__ bs) {
    __shared__ float sW[8 * 64];
    __shared__ float sb[64];
    for (int i = threadIdx.x; i < 512; i += blockDim.x) sW[i] = Ws[i];
    if (threadIdx.x < 64) sb[threadIdx.x] = bs[threadIdx.x];
    __syncthreads();
    int t = blockIdx.x * blockDim.x + threadIdx.x;
    if (t < 2 * NQ) {
        int g = (t >= NQ) ? 1 : 0;
        int i = g ? t - NQ : t;
        const float* p = g ? tpos : apos;
        float x = p[2 * i], y = p[2 * i + 1];
        atomicAdd(&g_ccnt[g * NCELL + cell_of(x) * GS + cell_of(y)], 1);
    }
#pragma unroll
    for (int rep = 0; rep < 2; rep++) {
        int it = t + rep * 320000;
        int n = it >> 6, c = it & 63;
        float acc = sb[c];
        const float* o = obs + n * 8;
#pragma unroll
        for (int i = 0; i < 8; i++) acc = fmaf(o[i], sW[i * 64 + c], acc);
        g_x[n * CDIM + c] = acc;
    }
}

// ---------------- 2) cell scans (2 blocks, one per graph) ------------------
__global__ void scan_kernel() {
    __shared__ int part[1024];
    int t = threadIdx.x;
    int gsel = blockIdx.x;
    const int* cnt = g_ccnt + gsel * NCELL;
    int* off = g_coff + gsel * (NCELL + 1);
    int* cur = g_ccur + gsel * NCELL;
    int base = t * 3, s = 0;
#pragma unroll
    for (int i = 0; i < 3; i++) { int j = base + i; if (j < NCELL) s += cnt[j]; }
    part[t] = s;
    __syncthreads();
    for (int d = 1; d < 1024; d <<= 1) {
        int v = 0;
        if (t >= d) v = part[t - d];
        __syncthreads();
        if (t >= d) part[t] += v;
        __syncthreads();
    }
    int run = t ? part[t - 1] : 0;
#pragma unroll
    for (int i = 0; i < 3; i++) {
        int j = base + i;
        if (j < NCELL) { off[j] = run; cur[j] = run; run += cnt[j]; }
    }
    if (t == 1023) off[NCELL] = part[1023];
}

// ---------------- 3) fused scatters: points + edges (padded CSR) -----------
__global__ void scatter_kernel(const float* __restrict__ apos,
                               const float* __restrict__ tpos,
                               const int* __restrict__ ei) {
    int t = blockIdx.x * blockDim.x + threadIdx.x;
    if (t < 2 * NQ) {
        int g = (t >= NQ) ? 1 : 0;
        int i = g ? t - NQ : t;
        const float* p = g ? tpos : apos;
        float x = p[2 * i], y = p[2 * i + 1];
        int c = g * NCELL + cell_of(x) * GS + cell_of(y);
        int pos = atomicAdd(&g_ccur[c], 1);
        g_cpos[g * NQ + pos] = make_float2(x, y);
        g_cidx[g * NQ + pos] = i;
    }
    if (t < NE) {
        int s = ei[t], d = ei[NE + t];
        int p = atomicAdd(&g_deg[d], 1);
        if (p < ESTRIDE) g_esrc[d * ESTRIDE + p] = s;
    }
}

// ---------------- 4) dd2/dd3: one load per lane + shuffle reduce -----------
__global__ void dd23_kernel(int phase) {     // 0: dd2 = S deg; 1: dd3 = S dd2
    int w = (blockIdx.x * blockDim.x + threadIdx.x) >> 5;
    if (w >= NQ) return;
    int lane = threadIdx.x & 31;
    int d = min(g_deg[w], ESTRIDE);
    float s = 0.f;
    for (int j = lane; j < d; j += 32) {
        int src = g_esrc[w * ESTRIDE + j];
        s += phase ? g_dd2[src] : (float)g_deg[src];
    }
#pragma unroll
    for (int o = 16; o > 0; o >>= 1) s += __shfl_xor_sync(0xffffffffu, s, o);
    if (lane == 0) { if (phase) g_dd3[w] = s; else g_dd2[w] = s; }
}

// ---------------- 5) radius top-10 via 3 contiguous y-spans ----------------
__global__ void radius_grid_kernel(const float* __restrict__ apos) {
    int graph = blockIdx.y;
    int q = blockIdx.x * blockDim.x + threadIdx.x;
    if (q >= NQ) return;
    float qx = apos[2 * q], qy = apos[2 * q + 1];
    const int* off = g_coff + graph * (NCELL + 1);
    const float2* cpos = g_cpos + graph * NQ;
    const int* cidx = g_cidx + graph * NQ;
    int cx0 = cell_of(qx), cy0 = cell_of(qy);
    int cylo = max(cy0 - 1, 0), cyhi = min(cy0 + 1, GS - 1);

    float bd[KNBR];
    int   bi[KNBR];
#pragma unroll
    for (int m = 0; m < KNBR; m++) { bd[m] = 4.0000005f; bi[m] = -1; }

    for (int dx = -1; dx <= 1; dx++) {
        int cx = cx0 + dx;
        if ((unsigned)cx >= GS) continue;
        int jb = off[cx * GS + cylo];
        int je = off[cx * GS + cyhi + 1];
        for (int j = jb; j < je; j++) {
            float2 kp = cpos[j];
            float ddx = qx - kp.x, ddy = qy - kp.y;
            float d2 = fmaf(ddy, ddy, ddx * ddx);
            if (d2 < bd[KNBR - 1]) {
                int ki = cidx[j];
                if (!(graph == 0 && ki == q)) {
                    float d = d2; int id = ki;
#pragma unroll
                    for (int m = 0; m < KNBR; m++) {
                        if (d < bd[m]) {
                            float td = bd[m]; int ti = bi[m];
                            bd[m] = d; bi[m] = id; d = td; id = ti;
                        }
                    }
                }
            }
        }
    }
    int* out = graph ? g_tidx_buf : g_aidx_buf;
#pragma unroll
    for (int m = 0; m < KNBR; m++)
        out[q * KNBR + m] = (bd[m] <= 4.0f) ? bi[m] : -1;
}

// ---------------- 6) GATv2 (one warp per query; DS == 32 == warp) ----------
__global__ void gat_kernel(const float* __restrict__ qpos,
                           const float* __restrict__ apos,
                           const float* __restrict__ tpos,
                           const float* __restrict__ agWl, const float* __restrict__ agWr,
                           const float* __restrict__ agAtt, const float* __restrict__ agB,
                           const float* __restrict__ tgWl, const float* __restrict__ tgWr,
                           const float* __restrict__ tgAtt, const float* __restrict__ tgB) {
    const int graph = blockIdx.y;
    const float *kp, *Wl, *Wr, *att, *bb;
    const int* idx;
    int off;
    if (graph == 0) { kp = apos; idx = g_aidx_buf; Wl = agWl; Wr = agWr; att = agAtt; bb = agB; off = 64; }
    else            { kp = tpos; idx = g_tidx_buf; Wl = tgWl; Wr = tgWr; att = tgAtt; bb = tgB; off = 96; }

    int gwarp = (blockIdx.x * blockDim.x + threadIdx.x) >> 5;
    int lane = threadIdx.x & 31;
    if (gwarp >= NQ) return;
    int n = gwarp;

    float wl0 = Wl[lane], wl1 = Wl[32 + lane];
    float wr0 = Wr[lane], wr1 = Wr[32 + lane];
    float ac = att[lane];
    float qx = qpos[2 * n], qy = qpos[2 * n + 1];
    float xr = fmaf(qy, wr1, qx * wr0);

    float xl[KNBR], sv[KNBR];
    int vk[KNBR];
#pragma unroll
    for (int k = 0; k < KNBR; k++) {
        int i = idx[n * KNBR + k];
        vk[k] = (i >= 0);
        float s;
        if (i >= 0) {
            float nx = kp[2 * i], ny = kp[2 * i + 1];
            float v = fmaf(ny, wl1, nx * wl0);
            xl[k] = v;
            float g = v + xr;
            g = (g > 0.f) ? g : 0.2f * g;
            s = g * ac;
#pragma unroll
            for (int o = 16; o > 0; o >>= 1) s += __shfl_xor_sync(0xffffffffu, s, o);
        } else {
            xl[k] = 0.f;
            s = -1e9f;
        }
        sv[k] = s;
    }
    float m = -1e9f;
#pragma unroll
    for (int k = 0; k < KNBR; k++) m = fmaxf(m, sv[k]);
    float denom = 1e-16f, outc = 0.f;
#pragma unroll
    for (int k = 0; k < KNBR; k++) {
        float p = vk[k] ? expf(sv[k] - m) : 0.f;
        denom += p;
        outc = fmaf(p, xl[k], outc);
    }
    g_x[n * CDIM + off + lane] = outc / denom + bb[lane];
}

// ---------------- 7) per-column partial sums of x (layer-0 input) ----------
__global__ void colmean_part_kernel() {
    int b = blockIdx.x;                       // 128 blocks
    int c = threadIdx.x;                      // 128 threads = columns
    float s = 0.f;
    for (int n = b; n < NQ; n += 128) s += g_x[n * CDIM + c];
    g_cpart[b * 128 + c] = s;
}

// ---------------- 8) fused: mean + corr + stats-zero + fp16 convert --------
__global__ void corrconv_kernel(const float* __restrict__ gfW, int layer) {
    __shared__ float xm[128];
    int tid = threadIdx.x;                    // 256
    if (tid < 128) {
        float s = 0.f;
        for (int b = 0; b < 128; b++) s += g_cpart[b * 128 + tid];
        xm[tid] = s * (1.0f / (float)NQ);
    }
    __syncthreads();
    if (blockIdx.x == 0 && tid < 256) g_stats[tid] = 0.f;
    if (blockIdx.x < 3 && tid < 128) {
        int k = blockIdx.x + 1;
        const float* Wk = gfW + layer * 4 * 128 * 128 + k * 128 * 128;
        float acc = 0.f;
        for (int mm = 0; mm < 128; mm++)
            acc = fmaf(xm[mm], Wk[mm * 128 + tid], acc);
        g_corr[(k - 1) * 128 + tid] = acc;
    }
    int NT = gridDim.x * blockDim.x;
    for (int i = blockIdx.x * blockDim.x + tid; i < NQ * 64; i += NT) {
        int n = i >> 6, c2 = i & 63;
        float2 v = *(const float2*)&g_x[n * CDIM + c2 * 2];
        ((__half2*)g_Hh)[n * 256 + c2] =
            __floats2half2_rn(v.x - xm[c2 * 2], v.y - xm[c2 * 2 + 1]);
    }
}

// ---------------- 9) one shift tap in fp16, output scaled by 1/8 -----------
// half-warp per row (16 lanes x 16B); 8 edges in flight per iter (MLP 8).
__global__ void __launch_bounds__(128) gather_h_kernel(int srcoff, int dstoff) {
    int gt = blockIdx.x * blockDim.x + threadIdx.x;
    int w = gt >> 5;
    if (w >= NQ) return;
    int lane = gt & 31;
    int hw = lane >> 4;
    int sub = lane & 15;
    const uint4* H4 = (const uint4*)g_Hh;      // row = 64 uint4
    int soff8 = srcoff >> 3;
    int b = w * ESTRIDE;
    int e = b + min(g_deg[w], ESTRIDE);

    float acc[8];
#pragma unroll
    for (int i = 0; i < 8; i++) acc[i] = 0.f;

    int j = b + hw;
    for (; j + 14 < e; j += 16) {              // 8 edges per half-warp iter
        int si[8];
#pragma unroll
        for (int q = 0; q < 8; q++) si[q] = __ldg(&g_esrc[j + q * 2]);
        uint4 v[8];
#pragma unroll
        for (int q = 0; q < 8; q++) v[q] = __ldg(&H4[si[q] * 64 + soff8 + sub]);
#pragma unroll
        for (int q = 0; q < 8; q++) {
            const __half2* h = (const __half2*)&v[q];
#pragma unroll
            for (int i = 0; i < 4; i++) {
                float2 f = __half22float2(h[i]);
                acc[2 * i]     += f.x;
                acc[2 * i + 1] += f.y;
            }
        }
    }
    for (; j < e; j += 2) {
        int s = __ldg(&g_esrc[j]);
        uint4 v = __ldg(&H4[s * 64 + soff8 + sub]);
        const __half2* h = (const __half2*)&v;
#pragma unroll
        for (int i = 0; i < 4; i++) {
            float2 f = __half22float2(h[i]);
            acc[2 * i]     += f.x;
            acc[2 * i + 1] += f.y;
        }
    }
#pragma unroll
    for (int i = 0; i < 8; i++)
        acc[i] += __shfl_down_sync(0xffffffffu, acc[i], 16);

    if (hw == 0) {
        uint4 o;
        __half2* oh = (__half2*)&o;
#pragma unroll
        for (int i = 0; i < 4; i++)
            oh[i] = __floats2half2_rn(acc[2 * i] * TAP_DOWN,
                                      acc[2 * i + 1] * TAP_DOWN);
        ((uint4*)g_Hh)[w * 64 + (dstoff >> 3) + sub] = o;
    }
}

// ---------------- 10) tensor-core GEMM (explicit mma.sync PTX) -------------
__global__ void __launch_bounds__(128) gemm_h_kernel(int layer) {
    __shared__ __half Bs[128][72];
    __shared__ float Cs[3][128];
    const __half* WT = g_WhT + layer * 512 * 128;
    int tid = threadIdx.x;
    int warp = tid >> 5;
    int lane = tid & 31;
    int row0 = blockIdx.x * 64 + warp * 16;
    int gr = lane >> 2;
    int kq = lane & 3;

#pragma unroll
    for (int j = 0; j < 3; j++) Cs[j][tid] = g_corr[j * 128 + tid];

    float acc[64];
#pragma unroll
    for (int i = 0; i < 64; i++) acc[i] = 0.f;

    const __half* A0 = g_Hh + (row0 + gr) * 512 + kq * 2;
    const __half* A1 = g_Hh + (row0 + gr + 8) * 512 + kq * 2;

    for (int kc = 0; kc < 512; kc += 64) {
        __syncthreads();
#pragma unroll
        for (int it = 0; it < 8; it++) {
            int item = tid + it * 128;
            int n = item >> 3, q = item & 7;
            *(uint4*)&Bs[n][q * 8] = *(const uint4*)&WT[n * 512 + kc + q * 8];
        }
        __syncthreads();
#pragma unroll
        for (int ks = 0; ks < 4; ks++) {
            int kk = kc + ks * 16;
            uint32_t a0 = *(const uint32_t*)(A0 + kk);
            uint32_t a1 = *(const uint32_t*)(A1 + kk);
            uint32_t a2 = *(const uint32_t*)(A0 + kk + 8);
            uint32_t a3 = *(const uint32_t*)(A1 + kk + 8);
#pragma unroll
            for (int tn = 0; tn < 16; tn++) {
                int n = tn * 8 + gr;
                uint32_t b0 = *(const uint32_t*)&Bs[n][ks * 16 + kq * 2];
                uint32_t b1 = *(const uint32_t*)&Bs[n][ks * 16 + kq * 2 + 8];
                asm volatile(
                    "mma.sync.aligned.m16n8k16.row.col.f32.f16.f16.f32 "
                    "{%0,%1,%2,%3}, {%4,%5,%6,%7}, {%8,%9}, {%0,%1,%2,%3};\n"
                    : "+f"(acc[tn * 4]), "+f"(acc[tn * 4 + 1]),
                      "+f"(acc[tn * 4 + 2]), "+f"(acc[tn * 4 + 3])
                    : "r"(a0), "r"(a1), "r"(a2), "r"(a3), "r"(b0), "r"(b1));
            }
        }
    }

    int ra = row0 + gr, rb = row0 + gr + 8;
    float d1a = (float)g_deg[min(ra, NQ - 1)], d1b = (float)g_deg[min(rb, NQ - 1)];
    float d2a = g_dd2[ra], d3a = g_dd3[ra];
    float d2b = g_dd2[rb], d3b = g_dd3[rb];
#pragma unroll
    for (int tn = 0; tn < 16; tn++) {
        int col = tn * 8 + kq * 2;
        float c1x = Cs[0][col], c1y = Cs[0][col + 1];
        float c2x = Cs[1][col], c2y = Cs[1][col + 1];
        float c3x = Cs[2][col], c3y = Cs[2][col + 1];
        float ax = acc[tn * 4]     + d1a * c1x + d2a * c2x + d3a * c3x;
        float ay = acc[tn * 4 + 1] + d1a * c1y + d2a * c2y + d3a * c3y;
        float bx = acc[tn * 4 + 2] + d1b * c1x + d2b * c2x + d3b * c3x;
        float by = acc[tn * 4 + 3] + d1b * c1y + d2b * c2y + d3b * c3y;
        *(float2*)&g_y[ra * 128 + col] = make_float2(ax, ay);
        *(float2*)&g_y[rb * 128 + col] = make_float2(bx, by);
    }
    __syncthreads();
    int rbase = blockIdx.x * 64;
    float s = 0.f, s2 = 0.f;
    for (int r = 0; r < 64; r++) {
        int rr = rbase + r;
        if (rr < NQ) {
            float v = g_y[rr * 128 + tid];
            s += v;
            s2 = fmaf(v, v, s2);
        }
    }
    atomicAdd(&g_stats[tid], s);
    atomicAdd(&g_stats[128 + tid], s2);
}

// ---------------- 11) layer-0 BN apply + residual + next-layer colsums -----
__global__ void bn_colsum_kernel(const float* __restrict__ gamma,
                                 const float* __restrict__ beta) {
    int c = threadIdx.x;
    int b = blockIdx.x;
    const float invN = 1.0f / (float)NQ;
    float mu = g_stats[c] * invN;
    float var = g_stats[128 + c] * invN - mu * mu;
    float rstd = rsqrtf(var + 1e-5f) * gamma[c];
    float bt = beta[c];
    float colsum = 0.f;
    for (int r = b; r < NQ; r += 128) {
        float h = (g_y[r * 128 + c] - mu) * rstd + bt;
        h = (h > 0.f) ? h : 0.01f * h;
        float xn = g_x[r * 128 + c] + h;
        g_x[r * 128 + c] = xn;
        colsum += xn;
    }
    g_cpart[b * 128 + c] = colsum;
}

// ---------------- 12) layer-1 BN apply + residual + readout ----------------
__global__ void bn_readout_kernel(const float* __restrict__ gamma,
                                  const float* __restrict__ beta,
                                  const float* __restrict__ Wr,
                                  const float* __restrict__ br,
                                  float* __restrict__ out) {
    __shared__ float red[8];
    int c = threadIdx.x;
    int warp = c >> 5, lane = c & 31;
    const float invN = 1.0f / (float)NQ;
    float mu = g_stats[c] * invN;
    float var = g_stats[128 + c] * invN - mu * mu;
    float rstd = rsqrtf(var + 1e-5f) * gamma[c];
    float bt = beta[c];
    float w0 = Wr[c * 2], w1 = Wr[c * 2 + 1];
    float b0 = br[0], b1 = br[1];
    for (int r = blockIdx.x; r < NQ; r += gridDim.x) {
        float h = (g_y[r * 128 + c] - mu) * rstd + bt;
        h = (h > 0.f) ? h : 0.01f * h;
        float xn = g_x[r * 128 + c] + h;
        float a0 = xn * w0, a1 = xn * w1;
#pragma unroll
        for (int o = 16; o > 0; o >>= 1) {
            a0 += __shfl_xor_sync(0xffffffffu, a0, o);
            a1 += __shfl_xor_sync(0xffffffffu, a1, o);
        }
        if (lane == 0) { red[warp * 2] = a0; red[warp * 2 + 1] = a1; }
        __syncthreads();
        if (c == 0)
            out[r * 2]     = (red[0] + red[2]) + (red[4] + red[6]) + b0;
        if (c == 1)
            out[r * 2 + 1] = (red[1] + red[3]) + (red[5] + red[7]) + b1;
        __syncthreads();
    }
}

// ---------------- launch ---------------------------------------------------
extern "C" void kernel_launch(void* const* d_in, const int* in_sizes, int n_in,
                              void* d_out, int out_size) {
    const float* own_obs = (const float*)d_in[0];
    const float* apos    = (const float*)d_in[1];
    const float* tpos    = (const float*)d_in[2];
    const float* W_self  = (const float*)d_in[3];
    const float* b_self  = (const float*)d_in[4];
    const float* ag_Wl   = (const float*)d_in[5];
    const float* ag_Wr   = (const float*)d_in[6];
    const float* ag_att  = (const float*)d_in[7];
    const float* ag_b    = (const float*)d_in[8];
    const float* tg_Wl   = (const float*)d_in[9];
    const float* tg_Wr   = (const float*)d_in[10];
    const float* tg_att  = (const float*)d_in[11];
    const float* tg_b    = (const float*)d_in[12];
    const float* gf_W    = (const float*)d_in[13];   // [2,4,128,128]
    const float* bn_g    = (const float*)d_in[15];
    const float* bn_b    = (const float*)d_in[16];
    const float* W_read  = (const float*)d_in[17];
    const float* b_read  = (const float*)d_in[18];
    const int*   ei      = (const int*)d_in[19];     // [2, NE]
    float* out = (float*)d_out;

    init_kernel<<<80, 256>>>(gf_W);
    count_selfmlp_kernel<<<1250, 256>>>(apos, tpos, own_obs, W_self, b_self);
    scan_kernel<<<2, 1024>>>();
    scatter_kernel<<<(NE + 255) / 256, 256>>>(apos, tpos, ei);
    dd23_kernel<<<1250, 256>>>(0);
    dd23_kernel<<<1250, 256>>>(1);

    dim3 rgrid((NQ + 255) / 256, 2);
    radius_grid_kernel<<<rgrid, 256>>>(apos);

    dim3 ggrid((NQ + 3) / 4, 2);
    gat_kernel<<<ggrid, 128>>>(apos, apos, tpos,
                               ag_Wl, ag_Wr, ag_att, ag_b,
                               tg_Wl, tg_Wr, tg_att, tg_b);

    colmean_part_kernel<<<128, 128>>>();

    // ---- layer 0 ----
    corrconv_kernel<<<80, 256>>>(gf_W, 0);
    gather_h_kernel<<<2500, 128>>>(0, 128);
    gather_h_kernel<<<2500, 128>>>(128, 256);
    gather_h_kernel<<<2500, 128>>>(256, 384);
    gemm_h_kernel<<<(NQ + 63) / 64, 128>>>(0);
    bn_colsum_kernel<<<128, 128>>>(bn_g, bn_b);

    // ---- layer 1 ----
    corrconv_kernel<<<80, 256>>>(gf_W, 1);
    gather_h_kernel<<<2500, 128>>>(0, 128);
    gather_h_kernel<<<2500, 128>>>(128, 256);
    gather_h_kernel<<<2500, 128>>>(256, 384);
    gemm_h_kernel<<<(NQ + 63) / 64, 128>>>(1);
    bn_readout_kernel<<<256, 128>>>(bn_g + 128, bn_b + 128,
                                    W_read, b_read, out);
}

// round 13
// speedup vs baseline: 1.0326x; 1.0326x over previous
#include <cuda_runtime.h>
#include <cuda_fp16.h>
#include <cstdint>
#include <math.h>

#define NQ 10000
#define NE 320000
#define KNBR 10
#define CDIM 128
#define MPAD 10048
#define GS 50
#define NCELL 2500
#define ESTRIDE 128                           // padded CSR slots per node

// taps stored scaled by 8^-k (exact exponent shifts); weights by 8^k.
#define TAP_DOWN 0.125f

// ---------------- scratch (device globals; no allocation allowed) ----------
__device__ float  g_x[MPAD * CDIM];          // node features (residual stream, fp32)
__device__ __half g_Hh[MPAD * 512];          // centered taps [h0'|h1'/8|h2'/64|h3'/512]
__device__ __half g_WhT[2 * 128 * 512];      // gf_W transposed [l][n][k], W_k * 8^k
__device__ float  g_y[MPAD * CDIM];          // graph-filter output
__device__ int    g_deg[NQ];                 // degree (also scatter cursor)
__device__ int    g_esrc[NQ * ESTRIDE];      // padded CSR: sources per dst
__device__ float  g_stats[256];              // [sum(128) | sumsq(128)]
// mean-correction machinery
__device__ float  g_cpart[128 * 128];        // partial column sums
__device__ float  g_corr[3 * 128];           // c_k = xbar @ W_k  (k=1..3)
__device__ float  g_dd2[MPAD];               // S^2 1
__device__ float  g_dd3[MPAD];               // S^3 1
// spatial grid (agents then targets)
__device__ int    g_ccnt[2 * NCELL];
__device__ int    g_coff[2 * (NCELL + 1)];
__device__ int    g_ccur[2 * NCELL];
__device__ float2 g_cpos[2 * NQ];
__device__ int    g_cidx[2 * NQ];
__device__ int    g_aidx_buf[NQ * KNBR];
__device__ int    g_tidx_buf[NQ * KNBR];

// ---------------- 0) init: zero counters/deg/dummy-row + convert weights ---
__global__ void init_kernel(const float* __restrict__ gfW) {
    int t = blockIdx.x * blockDim.x + threadIdx.x;
    if (t < 2 * NCELL) g_ccnt[t] = 0;
    if (t < NQ) g_deg[t] = 0;
    // dummy row NQ of g_Hh = all zeros (512 halves = 256 u32); gathers
    // redirect out-of-range edge slots here so they add exact 0.
    if (t < 256) ((uint32_t*)(g_Hh + NQ * 512))[t] = 0u;
    // WhT[l][n][k] = gf_W[l][k][n] * 8^(k/128), fp16
    for (int i = t; i < 2 * 512 * 128; i += gridDim.x * blockDim.x) {
        int l = i >> 16;
        int rem = i & 65535;
        int n = rem >> 9;
        int k = rem & 511;
        float up = (k < 128) ? 1.f : (k < 256) ? 8.f : (k < 384) ? 64.f : 512.f;
        g_WhT[i] = __float2half(gfW[(l << 16) + k * 128 + n] * up);
    }
}

// ---------------- 1) fused: cell counts (points only) + self MLP -----------
__device__ __forceinline__ int cell_of(float v) {
    int c = __float2int_rd(v * 0.5f);
    return min(max(c, 0), GS - 1);
}
__global__ void count_selfmlp_kernel(const float* __restrict__ apos,
                                     const float* __restrict__ tpos,
                                     const float* __restrict__ obs,
                                     const float* __restrict__ Ws,
                                     const float* __restrict__ bs) {
    __shared__ float sW[8 * 64];
    __shared__ float sb[64];
    for (int i = threadIdx.x; i < 512; i += blockDim.x) sW[i] = Ws[i];
    if (threadIdx.x < 64) sb[threadIdx.x] = bs[threadIdx.x];
    __syncthreads();
    int t = blockIdx.x * blockDim.x + threadIdx.x;
    if (t < 2 * NQ) {
        int g = (t >= NQ) ? 1 : 0;
        int i = g ? t - NQ : t;
        const float* p = g ? tpos : apos;
        float x = p[2 * i], y = p[2 * i + 1];
        atomicAdd(&g_ccnt[g * NCELL + cell_of(x) * GS + cell_of(y)], 1);
    }
#pragma unroll
    for (int rep = 0; rep < 2; rep++) {
        int it = t + rep * 320000;
        int n = it >> 6, c = it & 63;
        float acc = sb[c];
        const float* o = obs + n * 8;
#pragma unroll
        for (int i = 0; i < 8; i++) acc = fmaf(o[i], sW[i * 64 + c], acc);
        g_x[n * CDIM + c] = acc;
    }
}

// ---------------- 2) cell scans (2 blocks, one per graph) ------------------
__global__ void scan_kernel() {
    __shared__ int part[1024];
    int t = threadIdx.x;
    int gsel = blockIdx.x;
    const int* cnt = g_ccnt + gsel * NCELL;
    int* off = g_coff + gsel * (NCELL + 1);
    int* cur = g_ccur + gsel * NCELL;
    int base = t * 3, s = 0;
#pragma unroll
    for (int i = 0; i < 3; i++) { int j = base + i; if (j < NCELL) s += cnt[j]; }
    part[t] = s;
    __syncthreads();
    for (int d = 1; d < 1024; d <<= 1) {
        int v = 0;
        if (t >= d) v = part[t - d];
        __syncthreads();
        if (t >= d) part[t] += v;
        __syncthreads();
    }
    int run = t ? part[t - 1] : 0;
#pragma unroll
    for (int i = 0; i < 3; i++) {
        int j = base + i;
        if (j < NCELL) { off[j] = run; cur[j] = run; run += cnt[j]; }
    }
    if (t == 1023) off[NCELL] = part[1023];
}

// ---------------- 3) fused scatters: points + edges (padded CSR) -----------
__global__ void scatter_kernel(const float* __restrict__ apos,
                               const float* __restrict__ tpos,
                               const int* __restrict__ ei) {
    int t = blockIdx.x * blockDim.x + threadIdx.x;
    if (t < 2 * NQ) {
        int g = (t >= NQ) ? 1 : 0;
        int i = g ? t - NQ : t;
        const float* p = g ? tpos : apos;
        float x = p[2 * i], y = p[2 * i + 1];
        int c = g * NCELL + cell_of(x) * GS + cell_of(y);
        int pos = atomicAdd(&g_ccur[c], 1);
        g_cpos[g * NQ + pos] = make_float2(x, y);
        g_cidx[g * NQ + pos] = i;
    }
    if (t < NE) {
        int s = ei[t], d = ei[NE + t];
        int p = atomicAdd(&g_deg[d], 1);
        if (p < ESTRIDE) g_esrc[d * ESTRIDE + p] = s;
    }
}

// ---------------- 4) dd2/dd3: one load per lane + shuffle reduce -----------
__global__ void dd23_kernel(int phase) {     // 0: dd2 = S deg; 1: dd3 = S dd2
    int w = (blockIdx.x * blockDim.x + threadIdx.x) >> 5;
    if (w >= NQ) return;
    int lane = threadIdx.x & 31;
    int d = min(g_deg[w], ESTRIDE);
    float s = 0.f;
    for (int j = lane; j < d; j += 32) {
        int src = g_esrc[w * ESTRIDE + j];
        s += phase ? g_dd2[src] : (float)g_deg[src];
    }
#pragma unroll
    for (int o = 16; o > 0; o >>= 1) s += __shfl_xor_sync(0xffffffffu, s, o);
    if (lane == 0) { if (phase) g_dd3[w] = s; else g_dd2[w] = s; }
}

// ---------------- 5) radius top-10 via 3 contiguous y-spans ----------------
__global__ void radius_grid_kernel(const float* __restrict__ apos) {
    int graph = blockIdx.y;
    int q = blockIdx.x * blockDim.x + threadIdx.x;
    if (q >= NQ) return;
    float qx = apos[2 * q], qy = apos[2 * q + 1];
    const int* off = g_coff + graph * (NCELL + 1);
    const float2* cpos = g_cpos + graph * NQ;
    const int* cidx = g_cidx + graph * NQ;
    int cx0 = cell_of(qx), cy0 = cell_of(qy);
    int cylo = max(cy0 - 1, 0), cyhi = min(cy0 + 1, GS - 1);

    float bd[KNBR];
    int   bi[KNBR];
#pragma unroll
    for (int m = 0; m < KNBR; m++) { bd[m] = 4.0000005f; bi[m] = -1; }

    for (int dx = -1; dx <= 1; dx++) {
        int cx = cx0 + dx;
        if ((unsigned)cx >= GS) continue;
        int jb = off[cx * GS + cylo];
        int je = off[cx * GS + cyhi + 1];
        for (int j = jb; j < je; j++) {
            float2 kp = cpos[j];
            float ddx = qx - kp.x, ddy = qy - kp.y;
            float d2 = fmaf(ddy, ddy, ddx * ddx);
            if (d2 < bd[KNBR - 1]) {
                int ki = cidx[j];
                if (!(graph == 0 && ki == q)) {
                    float d = d2; int id = ki;
#pragma unroll
                    for (int m = 0; m < KNBR; m++) {
                        if (d < bd[m]) {
                            float td = bd[m]; int ti = bi[m];
                            bd[m] = d; bi[m] = id; d = td; id = ti;
                        }
                    }
                }
            }
        }
    }
    int* out = graph ? g_tidx_buf : g_aidx_buf;
#pragma unroll
    for (int m = 0; m < KNBR; m++)
        out[q * KNBR + m] = (bd[m] <= 4.0f) ? bi[m] : -1;
}

// ---------------- 6) GATv2 (one warp per query; DS == 32 == warp) ----------
__global__ void gat_kernel(const float* __restrict__ qpos,
                           const float* __restrict__ apos,
                           const float* __restrict__ tpos,
                           const float* __restrict__ agWl, const float* __restrict__ agWr,
                           const float* __restrict__ agAtt, const float* __restrict__ agB,
                           const float* __restrict__ tgWl, const float* __restrict__ tgWr,
                           const float* __restrict__ tgAtt, const float* __restrict__ tgB) {
    const int graph = blockIdx.y;
    const float *kp, *Wl, *Wr, *att, *bb;
    const int* idx;
    int off;
    if (graph == 0) { kp = apos; idx = g_aidx_buf; Wl = agWl; Wr = agWr; att = agAtt; bb = agB; off = 64; }
    else            { kp = tpos; idx = g_tidx_buf; Wl = tgWl; Wr = tgWr; att = tgAtt; bb = tgB; off = 96; }

    int gwarp = (blockIdx.x * blockDim.x + threadIdx.x) >> 5;
    int lane = threadIdx.x & 31;
    if (gwarp >= NQ) return;
    int n = gwarp;

    float wl0 = Wl[lane], wl1 = Wl[32 + lane];
    float wr0 = Wr[lane], wr1 = Wr[32 + lane];
    float ac = att[lane];
    float qx = qpos[2 * n], qy = qpos[2 * n + 1];
    float xr = fmaf(qy, wr1, qx * wr0);

    float xl[KNBR], sv[KNBR];
    int vk[KNBR];
#pragma unroll
    for (int k = 0; k < KNBR; k++) {
        int i = idx[n * KNBR + k];
        vk[k] = (i >= 0);
        float s;
        if (i >= 0) {
            float nx = kp[2 * i], ny = kp[2 * i + 1];
            float v = fmaf(ny, wl1, nx * wl0);
            xl[k] = v;
            float g = v + xr;
            g = (g > 0.f) ? g : 0.2f * g;
            s = g * ac;
#pragma unroll
            for (int o = 16; o > 0; o >>= 1) s += __shfl_xor_sync(0xffffffffu, s, o);
        } else {
            xl[k] = 0.f;
            s = -1e9f;
        }
        sv[k] = s;
    }
    float m = -1e9f;
#pragma unroll
    for (int k = 0; k < KNBR; k++) m = fmaxf(m, sv[k]);
    float denom = 1e-16f, outc = 0.f;
#pragma unroll
    for (int k = 0; k < KNBR; k++) {
        float p = vk[k] ? expf(sv[k] - m) : 0.f;
        denom += p;
        outc = fmaf(p, xl[k], outc);
    }
    g_x[n * CDIM + off + lane] = outc / denom + bb[lane];
}

// ---------------- 7) per-column partial sums of x (layer-0 input) ----------
__global__ void colmean_part_kernel() {
    int b = blockIdx.x;                       // 128 blocks
    int c = threadIdx.x;                      // 128 threads = columns
    float s = 0.f;
    for (int n = b; n < NQ; n += 128) s += g_x[n * CDIM + c];
    g_cpart[b * 128 + c] = s;
}

// ---------------- 8) fused: mean + corr + stats-zero + fp16 convert --------
__global__ void corrconv_kernel(const float* __restrict__ gfW, int layer) {
    __shared__ float xm[128];
    int tid = threadIdx.x;                    // 256
    if (tid < 128) {
        float s = 0.f;
        for (int b = 0; b < 128; b++) s += g_cpart[b * 128 + tid];
        xm[tid] = s * (1.0f / (float)NQ);
    }
    __syncthreads();
    if (blockIdx.x == 0 && tid < 256) g_stats[tid] = 0.f;
    if (blockIdx.x < 3 && tid < 128) {
        int k = blockIdx.x + 1;
        const float* Wk = gfW + layer * 4 * 128 * 128 + k * 128 * 128;
        float acc = 0.f;
        for (int mm = 0; mm < 128; mm++)
            acc = fmaf(xm[mm], Wk[mm * 128 + tid], acc);
        g_corr[(k - 1) * 128 + tid] = acc;
    }
    int NT = gridDim.x * blockDim.x;
    for (int i = blockIdx.x * blockDim.x + tid; i < NQ * 64; i += NT) {
        int n = i >> 6, c2 = i & 63;
        float2 v = *(const float2*)&g_x[n * CDIM + c2 * 2];
        ((__half2*)g_Hh)[n * 256 + c2] =
            __floats2half2_rn(v.x - xm[c2 * 2], v.y - xm[c2 * 2 + 1]);
    }
}

// ---------------- 9) one shift tap in fp16, output scaled by 1/8 -----------
// half-warp per row (16 lanes x 16B); predicated 8-edge batches, NO serial
// tail: out-of-range slots read the all-zero dummy row NQ.
__global__ void __launch_bounds__(128) gather_h_kernel(int srcoff, int dstoff) {
    int gt = blockIdx.x * blockDim.x + threadIdx.x;
    int w = gt >> 5;
    if (w >= NQ) return;
    int lane = gt & 31;
    int hw = lane >> 4;
    int sub = lane & 15;
    const uint4* H4 = (const uint4*)g_Hh;      // row = 64 uint4
    int soff8 = srcoff >> 3;
    int b = w * ESTRIDE;
    int e = b + min(g_deg[w], ESTRIDE);

    float acc[8];
#pragma unroll
    for (int i = 0; i < 8; i++) acc[i] = 0.f;

    for (int j = b + hw; j < e; j += 16) {     // 8 edges in flight, predicated
        int si[8];
#pragma unroll
        for (int q = 0; q < 8; q++) {
            int idx = j + q * 2;
            si[q] = NQ;                        // dummy zero row
            if (idx < e) si[q] = __ldg(&g_esrc[idx]);
        }
        uint4 v[8];
#pragma unroll
        for (int q = 0; q < 8; q++) v[q] = __ldg(&H4[si[q] * 64 + soff8 + sub]);
#pragma unroll
        for (int q = 0; q < 8; q++) {
            const __half2* h = (const __half2*)&v[q];
#pragma unroll
            for (int i = 0; i < 4; i++) {
                float2 f = __half22float2(h[i]);
                acc[2 * i]     += f.x;
                acc[2 * i + 1] += f.y;
            }
        }
    }
#pragma unroll
    for (int i = 0; i < 8; i++)
        acc[i] += __shfl_down_sync(0xffffffffu, acc[i], 16);

    if (hw == 0) {
        uint4 o;
        __half2* oh = (__half2*)&o;
#pragma unroll
        for (int i = 0; i < 4; i++)
            oh[i] = __floats2half2_rn(acc[2 * i] * TAP_DOWN,
                                      acc[2 * i + 1] * TAP_DOWN);
        ((uint4*)g_Hh)[w * 64 + (dstoff >> 3) + sub] = o;
    }
}

// ---------------- 10) tensor-core GEMM (explicit mma.sync PTX) -------------
__global__ void __launch_bounds__(128) gemm_h_kernel(int layer) {
    __shared__ __half Bs[128][72];
    __shared__ float Cs[3][128];
    const __half* WT = g_WhT + layer * 512 * 128;
    int tid = threadIdx.x;
    int warp = tid >> 5;
    int lane = tid & 31;
    int row0 = blockIdx.x * 64 + warp * 16;
    int gr = lane >> 2;
    int kq = lane & 3;

#pragma unroll
    for (int j = 0; j < 3; j++) Cs[j][tid] = g_corr[j * 128 + tid];

    float acc[64];
#pragma unroll
    for (int i = 0; i < 64; i++) acc[i] = 0.f;

    const __half* A0 = g_Hh + (row0 + gr) * 512 + kq * 2;
    const __half* A1 = g_Hh + (row0 + gr + 8) * 512 + kq * 2;

    for (int kc = 0; kc < 512; kc += 64) {
        __syncthreads();
#pragma unroll
        for (int it = 0; it < 8; it++) {
            int item = tid + it * 128;
            int n = item >> 3, q = item & 7;
            *(uint4*)&Bs[n][q * 8] = *(const uint4*)&WT[n * 512 + kc + q * 8];
        }
        __syncthreads();
#pragma unroll
        for (int ks = 0; ks < 4; ks++) {
            int kk = kc + ks * 16;
            uint32_t a0 = *(const uint32_t*)(A0 + kk);
            uint32_t a1 = *(const uint32_t*)(A1 + kk);
            uint32_t a2 = *(const uint32_t*)(A0 + kk + 8);
            uint32_t a3 = *(const uint32_t*)(A1 + kk + 8);
#pragma unroll
            for (int tn = 0; tn < 16; tn++) {
                int n = tn * 8 + gr;
                uint32_t b0 = *(const uint32_t*)&Bs[n][ks * 16 + kq * 2];
                uint32_t b1 = *(const uint32_t*)&Bs[n][ks * 16 + kq * 2 + 8];
                asm volatile(
                    "mma.sync.aligned.m16n8k16.row.col.f32.f16.f16.f32 "
                    "{%0,%1,%2,%3}, {%4,%5,%6,%7}, {%8,%9}, {%0,%1,%2,%3};\n"
                    : "+f"(acc[tn * 4]), "+f"(acc[tn * 4 + 1]),
                      "+f"(acc[tn * 4 + 2]), "+f"(acc[tn * 4 + 3])
                    : "r"(a0), "r"(a1), "r"(a2), "r"(a3), "r"(b0), "r"(b1));
            }
        }
    }

    int ra = row0 + gr, rb = row0 + gr + 8;
    float d1a = (float)g_deg[min(ra, NQ - 1)], d1b = (float)g_deg[min(rb, NQ - 1)];
    float d2a = g_dd2[ra], d3a = g_dd3[ra];
    float d2b = g_dd2[rb], d3b = g_dd3[rb];
#pragma unroll
    for (int tn = 0; tn < 16; tn++) {
        int col = tn * 8 + kq * 2;
        float c1x = Cs[0][col], c1y = Cs[0][col + 1];
        float c2x = Cs[1][col], c2y = Cs[1][col + 1];
        float c3x = Cs[2][col], c3y = Cs[2][col + 1];
        float ax = acc[tn * 4]     + d1a * c1x + d2a * c2x + d3a * c3x;
        float ay = acc[tn * 4 + 1] + d1a * c1y + d2a * c2y + d3a * c3y;
        float bx = acc[tn * 4 + 2] + d1b * c1x + d2b * c2x + d3b * c3x;
        float by = acc[tn * 4 + 3] + d1b * c1y + d2b * c2y + d3b * c3y;
        *(float2*)&g_y[ra * 128 + col] = make_float2(ax, ay);
        *(float2*)&g_y[rb * 128 + col] = make_float2(bx, by);
    }
    __syncthreads();
    int rbase = blockIdx.x * 64;
    float s = 0.f, s2 = 0.f;
    for (int r = 0; r < 64; r++) {
        int rr = rbase + r;
        if (rr < NQ) {
            float v = g_y[rr * 128 + tid];
            s += v;
            s2 = fmaf(v, v, s2);
        }
    }
    atomicAdd(&g_stats[tid], s);
    atomicAdd(&g_stats[128 + tid], s2);
}

// ---------------- 11) layer-0 BN apply + residual + next-layer colsums -----
__global__ void bn_colsum_kernel(const float* __restrict__ gamma,
                                 const float* __restrict__ beta) {
    int c = threadIdx.x;
    int b = blockIdx.x;
    const float invN = 1.0f / (float)NQ;
    float mu = g_stats[c] * invN;
    float var = g_stats[128 + c] * invN - mu * mu;
    float rstd = rsqrtf(var + 1e-5f) * gamma[c];
    float bt = beta[c];
    float colsum = 0.f;
    for (int r = b; r < NQ; r += 128) {
        float h = (g_y[r * 128 + c] - mu) * rstd + bt;
        h = (h > 0.f) ? h : 0.01f * h;
        float xn = g_x[r * 128 + c] + h;
        g_x[r * 128 + c] = xn;
        colsum += xn;
    }
    g_cpart[b * 128 + c] = colsum;
}

// ---------------- 12) layer-1 BN apply + residual + readout ----------------
__global__ void bn_readout_kernel(const float* __restrict__ gamma,
                                  const float* __restrict__ beta,
                                  const float* __restrict__ Wr,
                                  const float* __restrict__ br,
                                  float* __restrict__ out) {
    __shared__ float red[8];
    int c = threadIdx.x;
    int warp = c >> 5, lane = c & 31;
    const float invN = 1.0f / (float)NQ;
    float mu = g_stats[c] * invN;
    float var = g_stats[128 + c] * invN - mu * mu;
    float rstd = rsqrtf(var + 1e-5f) * gamma[c];
    float bt = beta[c];
    float w0 = Wr[c * 2], w1 = Wr[c * 2 + 1];
    float b0 = br[0], b1 = br[1];
    for (int r = blockIdx.x; r < NQ; r += gridDim.x) {
        float h = (g_y[r * 128 + c] - mu) * rstd + bt;
        h = (h > 0.f) ? h : 0.01f * h;
        float xn = g_x[r * 128 + c] + h;
        float a0 = xn * w0, a1 = xn * w1;
#pragma unroll
        for (int o = 16; o > 0; o >>= 1) {
            a0 += __shfl_xor_sync(0xffffffffu, a0, o);
            a1 += __shfl_xor_sync(0xffffffffu, a1, o);
        }
        if (lane == 0) { red[warp * 2] = a0; red[warp * 2 + 1] = a1; }
        __syncthreads();
        if (c == 0)
            out[r * 2]     = (red[0] + red[2]) + (red[4] + red[6]) + b0;
        if (c == 1)
            out[r * 2 + 1] = (red[1] + red[3]) + (red[5] + red[7]) + b1;
        __syncthreads();
    }
}

// ---------------- launch ---------------------------------------------------
extern "C" void kernel_launch(void* const* d_in, const int* in_sizes, int n_in,
                              void* d_out, int out_size) {
    const float* own_obs = (const float*)d_in[0];
    const float* apos    = (const float*)d_in[1];
    const float* tpos    = (const float*)d_in[2];
    const float* W_self  = (const float*)d_in[3];
    const float* b_self  = (const float*)d_in[4];
    const float* ag_Wl   = (const float*)d_in[5];
    const float* ag_Wr   = (const float*)d_in[6];
    const float* ag_att  = (const float*)d_in[7];
    const float* ag_b    = (const float*)d_in[8];
    const float* tg_Wl   = (const float*)d_in[9];
    const float* tg_Wr   = (const float*)d_in[10];
    const float* tg_att  = (const float*)d_in[11];
    const float* tg_b    = (const float*)d_in[12];
    const float* gf_W    = (const float*)d_in[13];   // [2,4,128,128]
    const float* bn_g    = (const float*)d_in[15];
    const float* bn_b    = (const float*)d_in[16];
    const float* W_read  = (const float*)d_in[17];
    const float* b_read  = (const float*)d_in[18];
    const int*   ei      = (const int*)d_in[19];     // [2, NE]
    float* out = (float*)d_out;

    init_kernel<<<80, 256>>>(gf_W);
    count_selfmlp_kernel<<<1250, 256>>>(apos, tpos, own_obs, W_self, b_self);
    scan_kernel<<<2, 1024>>>();
    scatter_kernel<<<(NE + 255) / 256, 256>>>(apos, tpos, ei);
    dd23_kernel<<<1250, 256>>>(0);
    dd23_kernel<<<1250, 256>>>(1);

    dim3 rgrid((NQ + 255) / 256, 2);
    radius_grid_kernel<<<rgrid, 256>>>(apos);

    dim3 ggrid((NQ + 3) / 4, 2);
    gat_kernel<<<ggrid, 128>>>(apos, apos, tpos,
                               ag_Wl, ag_Wr, ag_att, ag_b,
                               tg_Wl, tg_Wr, tg_att, tg_b);

    colmean_part_kernel<<<128, 128>>>();

    // ---- layer 0 ----
    corrconv_kernel<<<80, 256>>>(gf_W, 0);
    gather_h_kernel<<<2500, 128>>>(0, 128);
    gather_h_kernel<<<2500, 128>>>(128, 256);
    gather_h_kernel<<<2500, 128>>>(256, 384);
    gemm_h_kernel<<<(NQ + 63) / 64, 128>>>(0);
    bn_colsum_kernel<<<128, 128>>>(bn_g, bn_b);

    // ---- layer 1 ----
    corrconv_kernel<<<80, 256>>>(gf_W, 1);
    gather_h_kernel<<<2500, 128>>>(0, 128);
    gather_h_kernel<<<2500, 128>>>(128, 256);
    gather_h_kernel<<<2500, 128>>>(256, 384);
    gemm_h_kernel<<<(NQ + 63) / 64, 128>>>(1);
    bn_readout_kernel<<<256, 128>>>(bn_g + 128, bn_b + 128,
                                    W_read, b_read, out);
}

// round 14
// speedup vs baseline: 1.0422x; 1.0092x over previous
#include <cuda_runtime.h>
#include <cuda_fp16.h>
#include <cstdint>
#include <math.h>

#define NQ 10000
#define NE 320000
#define KNBR 10
#define CDIM 128
#define MPAD 10048
#define GS 50
#define NCELL 2500
#define ESTRIDE 128                           // padded CSR slots per node

// taps stored scaled by 8^-k (exact exponent shifts); weights by 8^k.
#define TAP_DOWN 0.125f

// ---------------- scratch (device globals; no allocation allowed) ----------
__device__ float  g_x[MPAD * CDIM];          // node features (residual stream, fp32)
__device__ __half g_Hh[MPAD * 512];          // centered taps [h0'|h1'/8|h2'/64|h3'/512]
__device__ __half g_WhT[2 * 128 * 512];      // gf_W transposed [l][n][k], W_k * 8^k
__device__ float  g_y[MPAD * CDIM];          // graph-filter output
__device__ int    g_deg[NQ];                 // degree (also scatter cursor)
__device__ int    g_esrc[NQ * ESTRIDE];      // padded CSR: sources per dst
__device__ float  g_stats[256];              // [sum(128) | sumsq(128)]
// mean-correction machinery
__device__ float  g_xmean0[128];             // layer-0 column mean (atomic accum)
__device__ float  g_xmean1[128];             // layer-1 column mean (atomic accum)
__device__ float  g_corr[3 * 128];           // c_k = xbar @ W_k  (k=1..3)
__device__ float  g_dd2[MPAD];               // S^2 1
__device__ float  g_dd3[MPAD];               // S^3 1
// spatial grid (agents then targets)
__device__ int    g_ccnt[2 * NCELL];
__device__ int    g_coff[2 * (NCELL + 1)];
__device__ int    g_ccur[2 * NCELL];
__device__ float2 g_cpos[2 * NQ];
__device__ int    g_cidx[2 * NQ];
__device__ int    g_aidx_buf[NQ * KNBR];
__device__ int    g_tidx_buf[NQ * KNBR];

// ---------------- 0) init: zero counters/means/dummy + convert weights -----
__global__ void init_kernel(const float* __restrict__ gfW) {
    int t = blockIdx.x * blockDim.x + threadIdx.x;
    if (t < 2 * NCELL) g_ccnt[t] = 0;
    if (t < NQ) g_deg[t] = 0;
    if (t < 128) { g_xmean0[t] = 0.f; g_xmean1[t] = 0.f; }
    // dummy row NQ of g_Hh = all zeros; gathers redirect OOB slots here.
    if (t < 256) ((uint32_t*)(g_Hh + NQ * 512))[t] = 0u;
    // coalesced read of gfW; strided write to WhT[l][n][k] = gfW[l][k][n]*8^k
    for (int i = t; i < 2 * 512 * 128; i += gridDim.x * blockDim.x) {
        int l = i >> 16;
        int rem = i & 65535;
        int k = rem >> 7;
        int n = rem & 127;
        float up = (k < 128) ? 1.f : (k < 256) ? 8.f : (k < 384) ? 64.f : 512.f;
        g_WhT[(l << 16) + n * 512 + k] = __float2half(gfW[i] * up);
    }
}

// ---------------- 1) fused: cell counts (points only) + self MLP -----------
__device__ __forceinline__ int cell_of(float v) {
    int c = __float2int_rd(v * 0.5f);
    return min(max(c, 0), GS - 1);
}
__global__ void count_selfmlp_kernel(const float* __restrict__ apos,
                                     const float* __restrict__ tpos,
                                     const float* __restrict__ obs,
                                     const float* __restrict__ Ws,
                                     const float* __restrict__ bs) {
    __shared__ float sW[8 * 64];
    __shared__ float sb[64];
    for (int i = threadIdx.x; i < 512; i += blockDim.x) sW[i] = Ws[i];
    if (threadIdx.x < 64) sb[threadIdx.x] = bs[threadIdx.x];
    __syncthreads();
    int t = blockIdx.x * blockDim.x + threadIdx.x;
    if (t < 2 * NQ) {
        int g = (t >= NQ) ? 1 : 0;
        int i = g ? t - NQ : t;
        const float* p = g ? tpos : apos;
        float x = p[2 * i], y = p[2 * i + 1];
        atomicAdd(&g_ccnt[g * NCELL + cell_of(x) * GS + cell_of(y)], 1);
    }
#pragma unroll
    for (int rep = 0; rep < 2; rep++) {
        int it = t + rep * 320000;
        int n = it >> 6, c = it & 63;
        float acc = sb[c];
        const float* o = obs + n * 8;
#pragma unroll
        for (int i = 0; i < 8; i++) acc = fmaf(o[i], sW[i * 64 + c], acc);
        g_x[n * CDIM + c] = acc;
    }
}

// ---------------- 2) cell scans (2 blocks, one per graph) ------------------
__global__ void scan_kernel() {
    __shared__ int part[1024];
    int t = threadIdx.x;
    int gsel = blockIdx.x;
    const int* cnt = g_ccnt + gsel * NCELL;
    int* off = g_coff + gsel * (NCELL + 1);
    int* cur = g_ccur + gsel * NCELL;
    int base = t * 3, s = 0;
#pragma unroll
    for (int i = 0; i < 3; i++) { int j = base + i; if (j < NCELL) s += cnt[j]; }
    part[t] = s;
    __syncthreads();
    for (int d = 1; d < 1024; d <<= 1) {
        int v = 0;
        if (t >= d) v = part[t - d];
        __syncthreads();
        if (t >= d) part[t] += v;
        __syncthreads();
    }
    int run = t ? part[t - 1] : 0;
#pragma unroll
    for (int i = 0; i < 3; i++) {
        int j = base + i;
        if (j < NCELL) { off[j] = run; cur[j] = run; run += cnt[j]; }
    }
    if (t == 1023) off[NCELL] = part[1023];
}

// ---------------- 3) fused scatters: points + edges (padded CSR) -----------
__global__ void scatter_kernel(const float* __restrict__ apos,
                               const float* __restrict__ tpos,
                               const int* __restrict__ ei) {
    int t = blockIdx.x * blockDim.x + threadIdx.x;
    if (t < 2 * NQ) {
        int g = (t >= NQ) ? 1 : 0;
        int i = g ? t - NQ : t;
        const float* p = g ? tpos : apos;
        float x = p[2 * i], y = p[2 * i + 1];
        int c = g * NCELL + cell_of(x) * GS + cell_of(y);
        int pos = atomicAdd(&g_ccur[c], 1);
        g_cpos[g * NQ + pos] = make_float2(x, y);
        g_cidx[g * NQ + pos] = i;
    }
    if (t < NE) {
        int s = ei[t], d = ei[NE + t];
        int p = atomicAdd(&g_deg[d], 1);
        if (p < ESTRIDE) g_esrc[d * ESTRIDE + p] = s;
    }
}

// ---------------- 4) dd2/dd3: one load per lane + shuffle reduce -----------
__global__ void dd23_kernel(int phase) {     // 0: dd2 = S deg; 1: dd3 = S dd2
    int w = (blockIdx.x * blockDim.x + threadIdx.x) >> 5;
    if (w >= NQ) return;
    int lane = threadIdx.x & 31;
    int d = min(g_deg[w], ESTRIDE);
    float s = 0.f;
    for (int j = lane; j < d; j += 32) {
        int src = g_esrc[w * ESTRIDE + j];
        s += phase ? g_dd2[src] : (float)g_deg[src];
    }
#pragma unroll
    for (int o = 16; o > 0; o >>= 1) s += __shfl_xor_sync(0xffffffffu, s, o);
    if (lane == 0) { if (phase) g_dd3[w] = s; else g_dd2[w] = s; }
}

// ---------------- 5) radius top-10 via 3 contiguous y-spans ----------------
__global__ void radius_grid_kernel(const float* __restrict__ apos) {
    int graph = blockIdx.y;
    int q = blockIdx.x * blockDim.x + threadIdx.x;
    if (q >= NQ) return;
    float qx = apos[2 * q], qy = apos[2 * q + 1];
    const int* off = g_coff + graph * (NCELL + 1);
    const float2* cpos = g_cpos + graph * NQ;
    const int* cidx = g_cidx + graph * NQ;
    int cx0 = cell_of(qx), cy0 = cell_of(qy);
    int cylo = max(cy0 - 1, 0), cyhi = min(cy0 + 1, GS - 1);

    float bd[KNBR];
    int   bi[KNBR];
#pragma unroll
    for (int m = 0; m < KNBR; m++) { bd[m] = 4.0000005f; bi[m] = -1; }

    for (int dx = -1; dx <= 1; dx++) {
        int cx = cx0 + dx;
        if ((unsigned)cx >= GS) continue;
        int jb = off[cx * GS + cylo];
        int je = off[cx * GS + cyhi + 1];
        for (int j = jb; j < je; j++) {
            float2 kp = cpos[j];
            float ddx = qx - kp.x, ddy = qy - kp.y;
            float d2 = fmaf(ddy, ddy, ddx * ddx);
            if (d2 < bd[KNBR - 1]) {
                int ki = cidx[j];
                if (!(graph == 0 && ki == q)) {
                    float d = d2; int id = ki;
#pragma unroll
                    for (int m = 0; m < KNBR; m++) {
                        if (d < bd[m]) {
                            float td = bd[m]; int ti = bi[m];
                            bd[m] = d; bi[m] = id; d = td; id = ti;
                        }
                    }
                }
            }
        }
    }
    int* out = graph ? g_tidx_buf : g_aidx_buf;
#pragma unroll
    for (int m = 0; m < KNBR; m++)
        out[q * KNBR + m] = (bd[m] <= 4.0f) ? bi[m] : -1;
}

// ---------------- 6) GATv2 (one warp per query; DS == 32 == warp) ----------
__global__ void gat_kernel(const float* __restrict__ qpos,
                           const float* __restrict__ apos,
                           const float* __restrict__ tpos,
                           const float* __restrict__ agWl, const float* __restrict__ agWr,
                           const float* __restrict__ agAtt, const float* __restrict__ agB,
                           const float* __restrict__ tgWl, const float* __restrict__ tgWr,
                           const float* __restrict__ tgAtt, const float* __restrict__ tgB) {
    const int graph = blockIdx.y;
    const float *kp, *Wl, *Wr, *att, *bb;
    const int* idx;
    int off;
    if (graph == 0) { kp = apos; idx = g_aidx_buf; Wl = agWl; Wr = agWr; att = agAtt; bb = agB; off = 64; }
    else            { kp = tpos; idx = g_tidx_buf; Wl = tgWl; Wr = tgWr; att = tgAtt; bb = tgB; off = 96; }

    int gwarp = (blockIdx.x * blockDim.x + threadIdx.x) >> 5;
    int lane = threadIdx.x & 31;
    if (gwarp >= NQ) return;
    int n = gwarp;

    float wl0 = Wl[lane], wl1 = Wl[32 + lane];
    float wr0 = Wr[lane], wr1 = Wr[32 + lane];
    float ac = att[lane];
    float qx = qpos[2 * n], qy = qpos[2 * n + 1];
    float xr = fmaf(qy, wr1, qx * wr0);

    float xl[KNBR], sv[KNBR];
    int vk[KNBR];
#pragma unroll
    for (int k = 0; k < KNBR; k++) {
        int i = idx[n * KNBR + k];
        vk[k] = (i >= 0);
        float s;
        if (i >= 0) {
            float nx = kp[2 * i], ny = kp[2 * i + 1];
            float v = fmaf(ny, wl1, nx * wl0);
            xl[k] = v;
            float g = v + xr;
            g = (g > 0.f) ? g : 0.2f * g;
            s = g * ac;
#pragma unroll
            for (int o = 16; o > 0; o >>= 1) s += __shfl_xor_sync(0xffffffffu, s, o);
        } else {
            xl[k] = 0.f;
            s = -1e9f;
        }
        sv[k] = s;
    }
    float m = -1e9f;
#pragma unroll
    for (int k = 0; k < KNBR; k++) m = fmaxf(m, sv[k]);
    float denom = 1e-16f, outc = 0.f;
#pragma unroll
    for (int k = 0; k < KNBR; k++) {
        float p = vk[k] ? expf(sv[k] - m) : 0.f;
        denom += p;
        outc = fmaf(p, xl[k], outc);
    }
    g_x[n * CDIM + off + lane] = outc / denom + bb[lane];
}

// ---------------- 7) column mean of x -> g_xmean0 (atomic, scaled) ---------
__global__ void colmean_kernel() {
    int b = blockIdx.x;                       // 128 blocks
    int c = threadIdx.x;                      // 128 threads = columns
    float s = 0.f;
    for (int n = b; n < NQ; n += 128) s += g_x[n * CDIM + c];
    atomicAdd(&g_xmean0[c], s * (1.0f / (float)NQ));
}

// ---------------- 8) fused: corr + stats-zero + fp16 convert ---------------
// xmean precomputed; blocks 0-2 do the 3 rank-1 weight dots; all blocks
// grid-stride the centered fp16 conversion.
__global__ void corrconv_kernel(const float* __restrict__ gfW, int layer,
                                const float* __restrict__ xmean) {
    __shared__ float xm[128];
    int tid = threadIdx.x;                    // 256
    if (tid < 128) xm[tid] = xmean[tid];
    __syncthreads();
    if (blockIdx.x == 0 && tid < 256) g_stats[tid] = 0.f;
    if (blockIdx.x < 3 && tid < 128) {
        int k = blockIdx.x + 1;
        const float* Wk = gfW + layer * 4 * 128 * 128 + k * 128 * 128;
        float acc = 0.f;
        for (int mm = 0; mm < 128; mm++)
            acc = fmaf(xm[mm], Wk[mm * 128 + tid], acc);
        g_corr[(k - 1) * 128 + tid] = acc;
    }
    int NT = gridDim.x * blockDim.x;
    for (int i = blockIdx.x * blockDim.x + tid; i < NQ * 64; i += NT) {
        int n = i >> 6, c2 = i & 63;
        float2 v = *(const float2*)&g_x[n * CDIM + c2 * 2];
        ((__half2*)g_Hh)[n * 256 + c2] =
            __floats2half2_rn(v.x - xm[c2 * 2], v.y - xm[c2 * 2 + 1]);
    }
}

// ---------------- 9) one shift tap in fp16, output scaled by 1/8 -----------
// half-warp per row (16 lanes x 16B); predicated 8-edge batches, no tail.
__global__ void __launch_bounds__(128) gather_h_kernel(int srcoff, int dstoff) {
    int gt = blockIdx.x * blockDim.x + threadIdx.x;
    int w = gt >> 5;
    if (w >= NQ) return;
    int lane = gt & 31;
    int hw = lane >> 4;
    int sub = lane & 15;
    const uint4* H4 = (const uint4*)g_Hh;      // row = 64 uint4
    int soff8 = srcoff >> 3;
    int b = w * ESTRIDE;
    int e = b + min(g_deg[w], ESTRIDE);

    float acc[8];
#pragma unroll
    for (int i = 0; i < 8; i++) acc[i] = 0.f;

    for (int j = b + hw; j < e; j += 16) {     // 8 edges in flight, predicated
        int si[8];
#pragma unroll
        for (int q = 0; q < 8; q++) {
            int idx = j + q * 2;
            si[q] = NQ;                        // dummy zero row
            if (idx < e) si[q] = __ldg(&g_esrc[idx]);
        }
        uint4 v[8];
#pragma unroll
        for (int q = 0; q < 8; q++) v[q] = __ldg(&H4[si[q] * 64 + soff8 + sub]);
#pragma unroll
        for (int q = 0; q < 8; q++) {
            const __half2* h = (const __half2*)&v[q];
#pragma unroll
            for (int i = 0; i < 4; i++) {
                float2 f = __half22float2(h[i]);
                acc[2 * i]     += f.x;
                acc[2 * i + 1] += f.y;
            }
        }
    }
#pragma unroll
    for (int i = 0; i < 8; i++)
        acc[i] += __shfl_down_sync(0xffffffffu, acc[i], 16);

    if (hw == 0) {
        uint4 o;
        __half2* oh = (__half2*)&o;
#pragma unroll
        for (int i = 0; i < 4; i++)
            oh[i] = __floats2half2_rn(acc[2 * i] * TAP_DOWN,
                                      acc[2 * i + 1] * TAP_DOWN);
        ((uint4*)g_Hh)[w * 64 + (dstoff >> 3) + sub] = o;
    }
}

// ---------------- 10) tensor-core GEMM (explicit mma.sync PTX) -------------
__global__ void __launch_bounds__(128) gemm_h_kernel(int layer) {
    __shared__ __half Bs[128][72];
    __shared__ float Cs[3][128];
    const __half* WT = g_WhT + layer * 512 * 128;
    int tid = threadIdx.x;
    int warp = tid >> 5;
    int lane = tid & 31;
    int row0 = blockIdx.x * 64 + warp * 16;
    int gr = lane >> 2;
    int kq = lane & 3;

#pragma unroll
    for (int j = 0; j < 3; j++) Cs[j][tid] = g_corr[j * 128 + tid];

    float acc[64];
#pragma unroll
    for (int i = 0; i < 64; i++) acc[i] = 0.f;

    const __half* A0 = g_Hh + (row0 + gr) * 512 + kq * 2;
    const __half* A1 = g_Hh + (row0 + gr + 8) * 512 + kq * 2;

    for (int kc = 0; kc < 512; kc += 64) {
        __syncthreads();
#pragma unroll
        for (int it = 0; it < 8; it++) {
            int item = tid + it * 128;
            int n = item >> 3, q = item & 7;
            *(uint4*)&Bs[n][q * 8] = *(const uint4*)&WT[n * 512 + kc + q * 8];
        }
        __syncthreads();
#pragma unroll
        for (int ks = 0; ks < 4; ks++) {
            int kk = kc + ks * 16;
            uint32_t a0 = *(const uint32_t*)(A0 + kk);
            uint32_t a1 = *(const uint32_t*)(A1 + kk);
            uint32_t a2 = *(const uint32_t*)(A0 + kk + 8);
            uint32_t a3 = *(const uint32_t*)(A1 + kk + 8);
#pragma unroll
            for (int tn = 0; tn < 16; tn++) {
                int n = tn * 8 + gr;
                uint32_t b0 = *(const uint32_t*)&Bs[n][ks * 16 + kq * 2];
                uint32_t b1 = *(const uint32_t*)&Bs[n][ks * 16 + kq * 2 + 8];
                asm volatile(
                    "mma.sync.aligned.m16n8k16.row.col.f32.f16.f16.f32 "
                    "{%0,%1,%2,%3}, {%4,%5,%6,%7}, {%8,%9}, {%0,%1,%2,%3};\n"
                    : "+f"(acc[tn * 4]), "+f"(acc[tn * 4 + 1]),
                      "+f"(acc[tn * 4 + 2]), "+f"(acc[tn * 4 + 3])
                    : "r"(a0), "r"(a1), "r"(a2), "r"(a3), "r"(b0), "r"(b1));
            }
        }
    }

    int ra = row0 + gr, rb = row0 + gr + 8;
    float d1a = (float)g_deg[min(ra, NQ - 1)], d1b = (float)g_deg[min(rb, NQ - 1)];
    float d2a = g_dd2[ra], d3a = g_dd3[ra];
    float d2b = g_dd2[rb], d3b = g_dd3[rb];
#pragma unroll
    for (int tn = 0; tn < 16; tn++) {
        int col = tn * 8 + kq * 2;
        float c1x = Cs[0][col], c1y = Cs[0][col + 1];
        float c2x = Cs[1][col], c2y = Cs[1][col + 1];
        float c3x = Cs[2][col], c3y = Cs[2][col + 1];
        float ax = acc[tn * 4]     + d1a * c1x + d2a * c2x + d3a * c3x;
        float ay = acc[tn * 4 + 1] + d1a * c1y + d2a * c2y + d3a * c3y;
        float bx = acc[tn * 4 + 2] + d1b * c1x + d2b * c2x + d3b * c3x;
        float by = acc[tn * 4 + 3] + d1b * c1y + d2b * c2y + d3b * c3y;
        *(float2*)&g_y[ra * 128 + col] = make_float2(ax, ay);
        *(float2*)&g_y[rb * 128 + col] = make_float2(bx, by);
    }
    __syncthreads();
    int rbase = blockIdx.x * 64;
    float s = 0.f, s2 = 0.f;
    for (int r = 0; r < 64; r++) {
        int rr = rbase + r;
        if (rr < NQ) {
            float v = g_y[rr * 128 + tid];
            s += v;
            s2 = fmaf(v, v, s2);
        }
    }
    atomicAdd(&g_stats[tid], s);
    atomicAdd(&g_stats[128 + tid], s2);
}

// ---------------- 11) layer-0 BN apply + residual + layer-1 colmean --------
__global__ void bn_colsum_kernel(const float* __restrict__ gamma,
                                 const float* __restrict__ beta) {
    int c = threadIdx.x;
    int b = blockIdx.x;
    const float invN = 1.0f / (float)NQ;
    float mu = g_stats[c] * invN;
    float var = g_stats[128 + c] * invN - mu * mu;
    float rstd = rsqrtf(var + 1e-5f) * gamma[c];
    float bt = beta[c];
    float colsum = 0.f;
    for (int r = b; r < NQ; r += 128) {
        float h = (g_y[r * 128 + c] - mu) * rstd + bt;
        h = (h > 0.f) ? h : 0.01f * h;
        float xn = g_x[r * 128 + c] + h;
        g_x[r * 128 + c] = xn;
        colsum += xn;
    }
    atomicAdd(&g_xmean1[c], colsum * invN);
}

// ---------------- 12) layer-1 BN apply + residual + readout ----------------
__global__ void bn_readout_kernel(const float* __restrict__ gamma,
                                  const float* __restrict__ beta,
                                  const float* __restrict__ Wr,
                                  const float* __restrict__ br,
                                  float* __restrict__ out) {
    __shared__ float red[8];
    int c = threadIdx.x;
    int warp = c >> 5, lane = c & 31;
    const float invN = 1.0f / (float)NQ;
    float mu = g_stats[c] * invN;
    float var = g_stats[128 + c] * invN - mu * mu;
    float rstd = rsqrtf(var + 1e-5f) * gamma[c];
    float bt = beta[c];
    float w0 = Wr[c * 2], w1 = Wr[c * 2 + 1];
    float b0 = br[0], b1 = br[1];
    for (int r = blockIdx.x; r < NQ; r += gridDim.x) {
        float h = (g_y[r * 128 + c] - mu) * rstd + bt;
        h = (h > 0.f) ? h : 0.01f * h;
        float xn = g_x[r * 128 + c] + h;
        float a0 = xn * w0, a1 = xn * w1;
#pragma unroll
        for (int o = 16; o > 0; o >>= 1) {
            a0 += __shfl_xor_sync(0xffffffffu, a0, o);
            a1 += __shfl_xor_sync(0xffffffffu, a1, o);
        }
        if (lane == 0) { red[warp * 2] = a0; red[warp * 2 + 1] = a1; }
        __syncthreads();
        if (c == 0)
            out[r * 2]     = (red[0] + red[2]) + (red[4] + red[6]) + b0;
        if (c == 1)
            out[r * 2 + 1] = (red[1] + red[3]) + (red[5] + red[7]) + b1;
        __syncthreads();
    }
}

// ---------------- launch ---------------------------------------------------
extern "C" void kernel_launch(void* const* d_in, const int* in_sizes, int n_in,
                              void* d_out, int out_size) {
    const float* own_obs = (const float*)d_in[0];
    const float* apos    = (const float*)d_in[1];
    const float* tpos    = (const float*)d_in[2];
    const float* W_self  = (const float*)d_in[3];
    const float* b_self  = (const float*)d_in[4];
    const float* ag_Wl   = (const float*)d_in[5];
    const float* ag_Wr   = (const float*)d_in[6];
    const float* ag_att  = (const float*)d_in[7];
    const float* ag_b    = (const float*)d_in[8];
    const float* tg_Wl   = (const float*)d_in[9];
    const float* tg_Wr   = (const float*)d_in[10];
    const float* tg_att  = (const float*)d_in[11];
    const float* tg_b    = (const float*)d_in[12];
    const float* gf_W    = (const float*)d_in[13];   // [2,4,128,128]
    const float* bn_g    = (const float*)d_in[15];
    const float* bn_b    = (const float*)d_in[16];
    const float* W_read  = (const float*)d_in[17];
    const float* b_read  = (const float*)d_in[18];
    const int*   ei      = (const int*)d_in[19];     // [2, NE]
    float* out = (float*)d_out;

    float* xm0; cudaGetSymbolAddress((void**)&xm0, g_xmean0);
    float* xm1; cudaGetSymbolAddress((void**)&xm1, g_xmean1);

    init_kernel<<<80, 256>>>(gf_W);
    count_selfmlp_kernel<<<1250, 256>>>(apos, tpos, own_obs, W_self, b_self);
    scan_kernel<<<2, 1024>>>();
    scatter_kernel<<<(NE + 255) / 256, 256>>>(apos, tpos, ei);
    dd23_kernel<<<1250, 256>>>(0);
    dd23_kernel<<<1250, 256>>>(1);

    dim3 rgrid((NQ + 255) / 256, 2);
    radius_grid_kernel<<<rgrid, 256>>>(apos);

    dim3 ggrid((NQ + 3) / 4, 2);
    gat_kernel<<<ggrid, 128>>>(apos, apos, tpos,
                               ag_Wl, ag_Wr, ag_att, ag_b,
                               tg_Wl, tg_Wr, tg_att, tg_b);

    colmean_kernel<<<128, 128>>>();

    // ---- layer 0 ----
    corrconv_kernel<<<80, 256>>>(gf_W, 0, xm0);
    gather_h_kernel<<<2500, 128>>>(0, 128);
    gather_h_kernel<<<2500, 128>>>(128, 256);
    gather_h_kernel<<<2500, 128>>>(256, 384);
    gemm_h_kernel<<<(NQ + 63) / 64, 128>>>(0);
    bn_colsum_kernel<<<128, 128>>>(bn_g, bn_b);

    // ---- layer 1 ----
    corrconv_kernel<<<80, 256>>>(gf_W, 1, xm1);
    gather_h_kernel<<<2500, 128>>>(0, 128);
    gather_h_kernel<<<2500, 128>>>(128, 256);
    gather_h_kernel<<<2500, 128>>>(256, 384);
    gemm_h_kernel<<<(NQ + 63) / 64, 128>>>(1);
    bn_readout_kernel<<<256, 128>>>(bn_g + 128, bn_b + 128,
                                    W_read, b_read, out);
}

// round 15
// speedup vs baseline: 1.1481x; 1.1016x over previous
#include <cuda_runtime.h>
#include <cuda_fp16.h>
#include <cstdint>
#include <math.h>

#define NQ 10000
#define NE 320000
#define KNBR 10
#define CDIM 128
#define MPAD 10048
#define GS 50
#define NCELL 2500
#define ESTRIDE 128                           // padded CSR slots per node

// taps stored scaled by 8^-k (exact exponent shifts); weights by 8^k.
#define TAP_DOWN 0.125f

// ---------------- scratch (device globals; no allocation allowed) ----------
__device__ float  g_x[MPAD * CDIM];          // node features (residual stream, fp32)
__device__ __half g_Hh[MPAD * 512];          // centered taps [h0'|h1'/8|h2'/64|h3'/512]
__device__ __half g_WhT[2 * 128 * 512];      // gf_W transposed [l][n][k], W_k * 8^k
__device__ float  g_y[MPAD * CDIM];          // graph-filter output
__device__ int    g_deg[NQ];                 // degree (also scatter cursor)
__device__ int    g_esrc[NQ * ESTRIDE];      // padded CSR: sources per dst
__device__ float  g_stats[256];              // [sum(128) | sumsq(128)]
// mean-correction machinery
__device__ float  g_xmean0[128];             // layer-0 column mean (atomic accum)
__device__ float  g_xmean1[128];             // layer-1 column mean (atomic accum)
__device__ float  g_corr[3 * 128];           // c_k = xbar @ W_k  (k=1..3)
__device__ float  g_dd2[MPAD];               // S^2 1
__device__ float  g_dd3[MPAD];               // S^3 1
// spatial grid (agents then targets)
__device__ int    g_ccnt[2 * NCELL];
__device__ int    g_coff[2 * (NCELL + 1)];
__device__ int    g_ccur[2 * NCELL];
__device__ float2 g_cpos[2 * NQ];
__device__ int    g_cidx[2 * NQ];
__device__ int    g_aidx_buf[NQ * KNBR];
__device__ int    g_tidx_buf[NQ * KNBR];

// ---------------- 0) init: zero counters/means/dummy + convert weights -----
__global__ void init_kernel(const float* __restrict__ gfW) {
    int t = blockIdx.x * blockDim.x + threadIdx.x;
    if (t < 2 * NCELL) g_ccnt[t] = 0;
    if (t < NQ) g_deg[t] = 0;
    if (t < 128) { g_xmean0[t] = 0.f; g_xmean1[t] = 0.f; }
    if (t < 256) ((uint32_t*)(g_Hh + NQ * 512))[t] = 0u;   // dummy zero row
    // coalesced read of gfW; strided write to WhT[l][n][k] = gfW[l][k][n]*8^k
    for (int i = t; i < 2 * 512 * 128; i += gridDim.x * blockDim.x) {
        int l = i >> 16;
        int rem = i & 65535;
        int k = rem >> 7;
        int n = rem & 127;
        float up = (k < 128) ? 1.f : (k < 256) ? 8.f : (k < 384) ? 64.f : 512.f;
        g_WhT[(l << 16) + n * 512 + k] = __float2half(gfW[i] * up);
    }
}

// ---------------- 1) fused: cell counts (points only) + self MLP -----------
__device__ __forceinline__ int cell_of(float v) {
    int c = __float2int_rd(v * 0.5f);
    return min(max(c, 0), GS - 1);
}
__global__ void count_selfmlp_kernel(const float* __restrict__ apos,
                                     const float* __restrict__ tpos,
                                     const float* __restrict__ obs,
                                     const float* __restrict__ Ws,
                                     const float* __restrict__ bs) {
    __shared__ float sW[8 * 64];
    __shared__ float sb[64];
    for (int i = threadIdx.x; i < 512; i += blockDim.x) sW[i] = Ws[i];
    if (threadIdx.x < 64) sb[threadIdx.x] = bs[threadIdx.x];
    __syncthreads();
    int t = blockIdx.x * blockDim.x + threadIdx.x;
    if (t < 2 * NQ) {
        int g = (t >= NQ) ? 1 : 0;
        int i = g ? t - NQ : t;
        const float* p = g ? tpos : apos;
        float x = p[2 * i], y = p[2 * i + 1];
        atomicAdd(&g_ccnt[g * NCELL + cell_of(x) * GS + cell_of(y)], 1);
    }
#pragma unroll
    for (int rep = 0; rep < 2; rep++) {
        int it = t + rep * 320000;
        int n = it >> 6, c = it & 63;
        float acc = sb[c];
        const float* o = obs + n * 8;
#pragma unroll
        for (int i = 0; i < 8; i++) acc = fmaf(o[i], sW[i * 64 + c], acc);
        g_x[n * CDIM + c] = acc;
    }
}

// ---------------- 2) cell scans (2 blocks, one per graph) ------------------
__global__ void scan_kernel() {
    __shared__ int part[1024];
    int t = threadIdx.x;
    int gsel = blockIdx.x;
    const int* cnt = g_ccnt + gsel * NCELL;
    int* off = g_coff + gsel * (NCELL + 1);
    int* cur = g_ccur + gsel * NCELL;
    int base = t * 3, s = 0;
#pragma unroll
    for (int i = 0; i < 3; i++) { int j = base + i; if (j < NCELL) s += cnt[j]; }
    part[t] = s;
    __syncthreads();
    for (int d = 1; d < 1024; d <<= 1) {
        int v = 0;
        if (t >= d) v = part[t - d];
        __syncthreads();
        if (t >= d) part[t] += v;
        __syncthreads();
    }
    int run = t ? part[t - 1] : 0;
#pragma unroll
    for (int i = 0; i < 3; i++) {
        int j = base + i;
        if (j < NCELL) { off[j] = run; cur[j] = run; run += cnt[j]; }
    }
    if (t == 1023) off[NCELL] = part[1023];
}

// ---------------- 3a) point scatter into cell-sorted arrays ----------------
__global__ void point_scatter_kernel(const float* __restrict__ apos,
                                     const float* __restrict__ tpos) {
    int t = blockIdx.x * blockDim.x + threadIdx.x;
    if (t >= 2 * NQ) return;
    int g = (t >= NQ) ? 1 : 0;
    int i = g ? t - NQ : t;
    const float* p = g ? tpos : apos;
    float x = p[2 * i], y = p[2 * i + 1];
    int c = g * NCELL + cell_of(x) * GS + cell_of(y);
    int pos = atomicAdd(&g_ccur[c], 1);
    g_cpos[g * NQ + pos] = make_float2(x, y);
    g_cidx[g * NQ + pos] = i;
}

// ---------------- 3b) edge scatter into padded CSR (separate stream) -------
__global__ void edge_scatter_kernel(const int* __restrict__ ei) {
    int t = blockIdx.x * blockDim.x + threadIdx.x;
    if (t >= NE) return;
    int s = ei[t], d = ei[NE + t];
    int p = atomicAdd(&g_deg[d], 1);
    if (p < ESTRIDE) g_esrc[d * ESTRIDE + p] = s;
}

// ---------------- 4) dd2/dd3: one load per lane + shuffle reduce -----------
__global__ void dd23_kernel(int phase) {     // 0: dd2 = S deg; 1: dd3 = S dd2
    int w = (blockIdx.x * blockDim.x + threadIdx.x) >> 5;
    if (w >= NQ) return;
    int lane = threadIdx.x & 31;
    int d = min(g_deg[w], ESTRIDE);
    float s = 0.f;
    for (int j = lane; j < d; j += 32) {
        int src = g_esrc[w * ESTRIDE + j];
        s += phase ? g_dd2[src] : (float)g_deg[src];
    }
#pragma unroll
    for (int o = 16; o > 0; o >>= 1) s += __shfl_xor_sync(0xffffffffu, s, o);
    if (lane == 0) { if (phase) g_dd3[w] = s; else g_dd2[w] = s; }
}

// ---------------- 5) radius top-10 via 3 contiguous y-spans ----------------
__global__ void radius_grid_kernel(const float* __restrict__ apos) {
    int graph = blockIdx.y;
    int q = blockIdx.x * blockDim.x + threadIdx.x;
    if (q >= NQ) return;
    float qx = apos[2 * q], qy = apos[2 * q + 1];
    const int* off = g_coff + graph * (NCELL + 1);
    const float2* cpos = g_cpos + graph * NQ;
    const int* cidx = g_cidx + graph * NQ;
    int cx0 = cell_of(qx), cy0 = cell_of(qy);
    int cylo = max(cy0 - 1, 0), cyhi = min(cy0 + 1, GS - 1);

    float bd[KNBR];
    int   bi[KNBR];
#pragma unroll
    for (int m = 0; m < KNBR; m++) { bd[m] = 4.0000005f; bi[m] = -1; }

    for (int dx = -1; dx <= 1; dx++) {
        int cx = cx0 + dx;
        if ((unsigned)cx >= GS) continue;
        int jb = off[cx * GS + cylo];
        int je = off[cx * GS + cyhi + 1];
        for (int j = jb; j < je; j++) {
            float2 kp = cpos[j];
            float ddx = qx - kp.x, ddy = qy - kp.y;
            float d2 = fmaf(ddy, ddy, ddx * ddx);
            if (d2 < bd[KNBR - 1]) {
                int ki = cidx[j];
                if (!(graph == 0 && ki == q)) {
                    float d = d2; int id = ki;
#pragma unroll
                    for (int m = 0; m < KNBR; m++) {
                        if (d < bd[m]) {
                            float td = bd[m]; int ti = bi[m];
                            bd[m] = d; bi[m] = id; d = td; id = ti;
                        }
                    }
                }
            }
        }
    }
    int* out = graph ? g_tidx_buf : g_aidx_buf;
#pragma unroll
    for (int m = 0; m < KNBR; m++)
        out[q * KNBR + m] = (bd[m] <= 4.0f) ? bi[m] : -1;
}

// ---------------- 6) GATv2 (one warp per query; DS == 32 == warp) ----------
__global__ void gat_kernel(const float* __restrict__ qpos,
                           const float* __restrict__ apos,
                           const float* __restrict__ tpos,
                           const float* __restrict__ agWl, const float* __restrict__ agWr,
                           const float* __restrict__ agAtt, const float* __restrict__ agB,
                           const float* __restrict__ tgWl, const float* __restrict__ tgWr,
                           const float* __restrict__ tgAtt, const float* __restrict__ tgB) {
    const int graph = blockIdx.y;
    const float *kp, *Wl, *Wr, *att, *bb;
    const int* idx;
    int off;
    if (graph == 0) { kp = apos; idx = g_aidx_buf; Wl = agWl; Wr = agWr; att = agAtt; bb = agB; off = 64; }
    else            { kp = tpos; idx = g_tidx_buf; Wl = tgWl; Wr = tgWr; att = tgAtt; bb = tgB; off = 96; }

    int gwarp = (blockIdx.x * blockDim.x + threadIdx.x) >> 5;
    int lane = threadIdx.x & 31;
    if (gwarp >= NQ) return;
    int n = gwarp;

    float wl0 = Wl[lane], wl1 = Wl[32 + lane];
    float wr0 = Wr[lane], wr1 = Wr[32 + lane];
    float ac = att[lane];
    float qx = qpos[2 * n], qy = qpos[2 * n + 1];
    float xr = fmaf(qy, wr1, qx * wr0);

    float xl[KNBR], sv[KNBR];
    int vk[KNBR];
#pragma unroll
    for (int k = 0; k < KNBR; k++) {
        int i = idx[n * KNBR + k];
        vk[k] = (i >= 0);
        float s;
        if (i >= 0) {
            float nx = kp[2 * i], ny = kp[2 * i + 1];
            float v = fmaf(ny, wl1, nx * wl0);
            xl[k] = v;
            float g = v + xr;
            g = (g > 0.f) ? g : 0.2f * g;
            s = g * ac;
#pragma unroll
            for (int o = 16; o > 0; o >>= 1) s += __shfl_xor_sync(0xffffffffu, s, o);
        } else {
            xl[k] = 0.f;
            s = -1e9f;
        }
        sv[k] = s;
    }
    float m = -1e9f;
#pragma unroll
    for (int k = 0; k < KNBR; k++) m = fmaxf(m, sv[k]);
    float denom = 1e-16f, outc = 0.f;
#pragma unroll
    for (int k = 0; k < KNBR; k++) {
        float p = vk[k] ? expf(sv[k] - m) : 0.f;
        denom += p;
        outc = fmaf(p, xl[k], outc);
    }
    g_x[n * CDIM + off + lane] = outc / denom + bb[lane];
}

// ---------------- 7) column mean of x -> g_xmean0 (atomic, scaled) ---------
__global__ void colmean_kernel() {
    int b = blockIdx.x;
    int c = threadIdx.x;
    float s = 0.f;
    for (int n = b; n < NQ; n += 128) s += g_x[n * CDIM + c];
    atomicAdd(&g_xmean0[c], s * (1.0f / (float)NQ));
}

// ---------------- 8) fused: corr + stats-zero + fp16 convert ---------------
__global__ void corrconv_kernel(const float* __restrict__ gfW, int layer,
                                const float* __restrict__ xmean) {
    __shared__ float xm[128];
    int tid = threadIdx.x;                    // 256
    if (tid < 128) xm[tid] = xmean[tid];
    __syncthreads();
    if (blockIdx.x == 0 && tid < 256) g_stats[tid] = 0.f;
    if (blockIdx.x < 3 && tid < 128) {
        int k = blockIdx.x + 1;
        const float* Wk = gfW + layer * 4 * 128 * 128 + k * 128 * 128;
        float acc = 0.f;
        for (int mm = 0; mm < 128; mm++)
            acc = fmaf(xm[mm], Wk[mm * 128 + tid], acc);
        g_corr[(k - 1) * 128 + tid] = acc;
    }
    int NT = gridDim.x * blockDim.x;
    for (int i = blockIdx.x * blockDim.x + tid; i < NQ * 64; i += NT) {
        int n = i >> 6, c2 = i & 63;
        float2 v = *(const float2*)&g_x[n * CDIM + c2 * 2];
        ((__half2*)g_Hh)[n * 256 + c2] =
            __floats2half2_rn(v.x - xm[c2 * 2], v.y - xm[c2 * 2 + 1]);
    }
}

// ---------------- 9) one shift tap in fp16, output scaled by 1/8 -----------
// half-warp per row; predicated 8-edge batches, no tail (dummy zero row).
__global__ void __launch_bounds__(256) gather_h_kernel(int srcoff, int dstoff) {
    int gt = blockIdx.x * blockDim.x + threadIdx.x;
    int w = gt >> 5;
    if (w >= NQ) return;
    int lane = gt & 31;
    int hw = lane >> 4;
    int sub = lane & 15;
    const uint4* H4 = (const uint4*)g_Hh;      // row = 64 uint4
    int soff8 = srcoff >> 3;
    int b = w * ESTRIDE;
    int e = b + min(g_deg[w], ESTRIDE);

    float acc[8];
#pragma unroll
    for (int i = 0; i < 8; i++) acc[i] = 0.f;

    for (int j = b + hw; j < e; j += 16) {
        int si[8];
#pragma unroll
        for (int q = 0; q < 8; q++) {
            int idx = j + q * 2;
            si[q] = NQ;
            if (idx < e) si[q] = __ldg(&g_esrc[idx]);
        }
        uint4 v[8];
#pragma unroll
        for (int q = 0; q < 8; q++) v[q] = __ldg(&H4[si[q] * 64 + soff8 + sub]);
#pragma unroll
        for (int q = 0; q < 8; q++) {
            const __half2* h = (const __half2*)&v[q];
#pragma unroll
            for (int i = 0; i < 4; i++) {
                float2 f = __half22float2(h[i]);
                acc[2 * i]     += f.x;
                acc[2 * i + 1] += f.y;
            }
        }
    }
#pragma unroll
    for (int i = 0; i < 8; i++)
        acc[i] += __shfl_down_sync(0xffffffffu, acc[i], 16);

    if (hw == 0) {
        uint4 o;
        __half2* oh = (__half2*)&o;
#pragma unroll
        for (int i = 0; i < 4; i++)
            oh[i] = __floats2half2_rn(acc[2 * i] * TAP_DOWN,
                                      acc[2 * i + 1] * TAP_DOWN);
        ((uint4*)g_Hh)[w * 64 + (dstoff >> 3) + sub] = o;
    }
}

// ---------------- 10) tensor-core GEMM (explicit mma.sync PTX) -------------
__global__ void __launch_bounds__(128) gemm_h_kernel(int layer) {
    __shared__ __half Bs[128][72];
    __shared__ float Cs[3][128];
    const __half* WT = g_WhT + layer * 512 * 128;
    int tid = threadIdx.x;
    int warp = tid >> 5;
    int lane = tid & 31;
    int row0 = blockIdx.x * 64 + warp * 16;
    int gr = lane >> 2;
    int kq = lane & 3;

#pragma unroll
    for (int j = 0; j < 3; j++) Cs[j][tid] = g_corr[j * 128 + tid];

    float acc[64];
#pragma unroll
    for (int i = 0; i < 64; i++) acc[i] = 0.f;

    const __half* A0 = g_Hh + (row0 + gr) * 512 + kq * 2;
    const __half* A1 = g_Hh + (row0 + gr + 8) * 512 + kq * 2;

    for (int kc = 0; kc < 512; kc += 64) {
        __syncthreads();
#pragma unroll
        for (int it = 0; it < 8; it++) {
            int item = tid + it * 128;
            int n = item >> 3, q = item & 7;
            *(uint4*)&Bs[n][q * 8] = *(const uint4*)&WT[n * 512 + kc + q * 8];
        }
        __syncthreads();
#pragma unroll
        for (int ks = 0; ks < 4; ks++) {
            int kk = kc + ks * 16;
            uint32_t a0 = *(const uint32_t*)(A0 + kk);
            uint32_t a1 = *(const uint32_t*)(A1 + kk);
            uint32_t a2 = *(const uint32_t*)(A0 + kk + 8);
            uint32_t a3 = *(const uint32_t*)(A1 + kk + 8);
#pragma unroll
            for (int tn = 0; tn < 16; tn++) {
                int n = tn * 8 + gr;
                uint32_t b0 = *(const uint32_t*)&Bs[n][ks * 16 + kq * 2];
                uint32_t b1 = *(const uint32_t*)&Bs[n][ks * 16 + kq * 2 + 8];
                asm volatile(
                    "mma.sync.aligned.m16n8k16.row.col.f32.f16.f16.f32 "
                    "{%0,%1,%2,%3}, {%4,%5,%6,%7}, {%8,%9}, {%0,%1,%2,%3};\n"
                    : "+f"(acc[tn * 4]), "+f"(acc[tn * 4 + 1]),
                      "+f"(acc[tn * 4 + 2]), "+f"(acc[tn * 4 + 3])
                    : "r"(a0), "r"(a1), "r"(a2), "r"(a3), "r"(b0), "r"(b1));
            }
        }
    }

    int ra = row0 + gr, rb = row0 + gr + 8;
    float d1a = (float)g_deg[min(ra, NQ - 1)], d1b = (float)g_deg[min(rb, NQ - 1)];
    float d2a = g_dd2[ra], d3a = g_dd3[ra];
    float d2b = g_dd2[rb], d3b = g_dd3[rb];
#pragma unroll
    for (int tn = 0; tn < 16; tn++) {
        int col = tn * 8 + kq * 2;
        float c1x = Cs[0][col], c1y = Cs[0][col + 1];
        float c2x = Cs[1][col], c2y = Cs[1][col + 1];
        float c3x = Cs[2][col], c3y = Cs[2][col + 1];
        float ax = acc[tn * 4]     + d1a * c1x + d2a * c2x + d3a * c3x;
        float ay = acc[tn * 4 + 1] + d1a * c1y + d2a * c2y + d3a * c3y;
        float bx = acc[tn * 4 + 2] + d1b * c1x + d2b * c2x + d3b * c3x;
        float by = acc[tn * 4 + 3] + d1b * c1y + d2b * c2y + d3b * c3y;
        *(float2*)&g_y[ra * 128 + col] = make_float2(ax, ay);
        *(float2*)&g_y[rb * 128 + col] = make_float2(bx, by);
    }
    __syncthreads();
    int rbase = blockIdx.x * 64;
    float s = 0.f, s2 = 0.f;
    for (int r = 0; r < 64; r++) {
        int rr = rbase + r;
        if (rr < NQ) {
            float v = g_y[rr * 128 + tid];
            s += v;
            s2 = fmaf(v, v, s2);
        }
    }
    atomicAdd(&g_stats[tid], s);
    atomicAdd(&g_stats[128 + tid], s2);
}

// ---------------- 11) layer-0 BN apply + residual + layer-1 colmean --------
__global__ void bn_colsum_kernel(const float* __restrict__ gamma,
                                 const float* __restrict__ beta) {
    int c = threadIdx.x;
    int b = blockIdx.x;
    const float invN = 1.0f / (float)NQ;
    float mu = g_stats[c] * invN;
    float var = g_stats[128 + c] * invN - mu * mu;
    float rstd = rsqrtf(var + 1e-5f) * gamma[c];
    float bt = beta[c];
    float colsum = 0.f;
    for (int r = b; r < NQ; r += 128) {
        float h = (g_y[r * 128 + c] - mu) * rstd + bt;
        h = (h > 0.f) ? h : 0.01f * h;
        float xn = g_x[r * 128 + c] + h;
        g_x[r * 128 + c] = xn;
        colsum += xn;
    }
    atomicAdd(&g_xmean1[c], colsum * invN);
}

// ---------------- 12) layer-1 BN + residual + readout (warp per row) -------
__global__ void __launch_bounds__(256) bn_readout_kernel(
        const float* __restrict__ gamma, const float* __restrict__ beta,
        const float* __restrict__ Wr, const float* __restrict__ br,
        float* __restrict__ out) {
    int lane = threadIdx.x & 31;
    int wid = threadIdx.x >> 5;
    int gwarp = blockIdx.x * 8 + wid;
    const float invN = 1.0f / (float)NQ;
    float mu[4], rs[4], bt[4], w0[4], w1[4];
#pragma unroll
    for (int k2 = 0; k2 < 4; k2++) {
        int c = lane + k2 * 32;
        float m = g_stats[c] * invN;
        float var = g_stats[128 + c] * invN - m * m;
        mu[k2] = m;
        rs[k2] = rsqrtf(var + 1e-5f) * gamma[c];
        bt[k2] = beta[c];
        w0[k2] = Wr[c * 2];
        w1[k2] = Wr[c * 2 + 1];
    }
    float b0 = br[0], b1 = br[1];
    for (int r = gwarp; r < NQ; r += gridDim.x * 8) {
        float a0 = 0.f, a1 = 0.f;
#pragma unroll
        for (int k2 = 0; k2 < 4; k2++) {
            int c = lane + k2 * 32;
            float h = (g_y[r * 128 + c] - mu[k2]) * rs[k2] + bt[k2];
            h = (h > 0.f) ? h : 0.01f * h;
            float xn = g_x[r * 128 + c] + h;
            a0 = fmaf(xn, w0[k2], a0);
            a1 = fmaf(xn, w1[k2], a1);
        }
#pragma unroll
        for (int o = 16; o > 0; o >>= 1) {
            a0 += __shfl_xor_sync(0xffffffffu, a0, o);
            a1 += __shfl_xor_sync(0xffffffffu, a1, o);
        }
        if (lane == 0) {
            out[r * 2]     = a0 + b0;
            out[r * 2 + 1] = a1 + b1;
        }
    }
}

// ---------------- launch ---------------------------------------------------
extern "C" void kernel_launch(void* const* d_in, const int* in_sizes, int n_in,
                              void* d_out, int out_size) {
    const float* own_obs = (const float*)d_in[0];
    const float* apos    = (const float*)d_in[1];
    const float* tpos    = (const float*)d_in[2];
    const float* W_self  = (const float*)d_in[3];
    const float* b_self  = (const float*)d_in[4];
    const float* ag_Wl   = (const float*)d_in[5];
    const float* ag_Wr   = (const float*)d_in[6];
    const float* ag_att  = (const float*)d_in[7];
    const float* ag_b    = (const float*)d_in[8];
    const float* tg_Wl   = (const float*)d_in[9];
    const float* tg_Wr   = (const float*)d_in[10];
    const float* tg_att  = (const float*)d_in[11];
    const float* tg_b    = (const float*)d_in[12];
    const float* gf_W    = (const float*)d_in[13];   // [2,4,128,128]
    const float* bn_g    = (const float*)d_in[15];
    const float* bn_b    = (const float*)d_in[16];
    const float* W_read  = (const float*)d_in[17];
    const float* b_read  = (const float*)d_in[18];
    const int*   ei      = (const int*)d_in[19];     // [2, NE]
    float* out = (float*)d_out;

    float* xm0; cudaGetSymbolAddress((void**)&xm0, g_xmean0);
    float* xm1; cudaGetSymbolAddress((void**)&xm1, g_xmean1);

    // one-time side-stream resources (no device allocation)
    static cudaStream_t s2 = nullptr;
    static cudaEvent_t evFork = nullptr, evJoin = nullptr;
    if (!s2) {
        cudaStreamCreateWithFlags(&s2, cudaStreamNonBlocking);
        cudaEventCreateWithFlags(&evFork, cudaEventDisableTiming);
        cudaEventCreateWithFlags(&evJoin, cudaEventDisableTiming);
    }

    init_kernel<<<80, 256>>>(gf_W);

    // fork: edge pipeline runs concurrent with the points pipeline
    cudaEventRecord(evFork, 0);
    cudaStreamWaitEvent(s2, evFork, 0);
    edge_scatter_kernel<<<(NE + 255) / 256, 256, 0, s2>>>(ei);
    dd23_kernel<<<1250, 256, 0, s2>>>(0);
    dd23_kernel<<<1250, 256, 0, s2>>>(1);
    cudaEventRecord(evJoin, s2);

    // points pipeline (main stream)
    count_selfmlp_kernel<<<1250, 256>>>(apos, tpos, own_obs, W_self, b_self);
    scan_kernel<<<2, 1024>>>();
    point_scatter_kernel<<<(2 * NQ + 255) / 256, 256>>>(apos, tpos);

    dim3 rgrid((NQ + 255) / 256, 2);
    radius_grid_kernel<<<rgrid, 256>>>(apos);

    dim3 ggrid((NQ + 3) / 4, 2);
    gat_kernel<<<ggrid, 128>>>(apos, apos, tpos,
                               ag_Wl, ag_Wr, ag_att, ag_b,
                               tg_Wl, tg_Wr, tg_att, tg_b);

    colmean_kernel<<<128, 128>>>();
    corrconv_kernel<<<80, 256>>>(gf_W, 0, xm0);

    // join: gathers need esrc/deg from the edge pipeline
    cudaStreamWaitEvent(0, evJoin, 0);

    // ---- layer 0 ----
    gather_h_kernel<<<1250, 256>>>(0, 128);
    gather_h_kernel<<<1250, 256>>>(128, 256);
    gather_h_kernel<<<1250, 256>>>(256, 384);
    gemm_h_kernel<<<(NQ + 63) / 64, 128>>>(0);
    bn_colsum_kernel<<<128, 128>>>(bn_g, bn_b);

    // ---- layer 1 ----
    corrconv_kernel<<<80, 256>>>(gf_W, 1, xm1);
    gather_h_kernel<<<1250, 256>>>(0, 128);
    gather_h_kernel<<<1250, 256>>>(128, 256);
    gather_h_kernel<<<1250, 256>>>(256, 384);
    gemm_h_kernel<<<(NQ + 63) / 64, 128>>>(1);
    bn_readout_kernel<<<313, 256>>>(bn_g + 128, bn_b + 128,
                                    W_read, b_read, out);
}